// round 7
// baseline (speedup 1.0000x reference)
#include <cuda_runtime.h>
#include <cuda_bf16.h>
#include <math.h>
#include <stdint.h>

// Problem constants
#define ROWS   4096          // B*S
#define DMODEL 2048
#define NPROJ  8192          // 4*DMODEL
#define HEADS  16
#define HD     128
#define SEQ    2048
#define NB     2
#define FP16MAX 65504.0f
#define RMS_EPS 1e-5f
#define ATTN_SCALE 0.08838834764831845f

// ---------------- scratch (allocation-free) ----------------
#define HSD ((size_t)NB * HEADS * SEQ * HD)
__device__ __nv_bfloat16 g_qh[HSD], g_ql[HSD];
__device__ __nv_bfloat16 g_kh[HSD], g_kl[HSD];
__device__ __nv_bfloat16 g_vh[HSD], g_vl[HSD];
__device__ float         g_gate[HSD];
__device__ __nv_bfloat16 g_ahi [(size_t)ROWS * DMODEL];
__device__ __nv_bfloat16 g_alo [(size_t)ROWS * DMODEL];
__device__ __nv_bfloat16 g_winh[(size_t)NPROJ * DMODEL];
__device__ __nv_bfloat16 g_winl[(size_t)NPROJ * DMODEL];
__device__ __nv_bfloat16 g_woh [(size_t)DMODEL * DMODEL];
__device__ __nv_bfloat16 g_wol [(size_t)DMODEL * DMODEL];
__device__ __nv_bfloat16 g_th  [(size_t)ROWS * DMODEL];
__device__ __nv_bfloat16 g_tl  [(size_t)ROWS * DMODEL];

// ---------------- PTX helpers ----------------
__device__ __forceinline__ uint32_t smem_u32(const void* p) {
    uint32_t a;
    asm("{ .reg .u64 t; cvta.to.shared.u64 t, %1; cvt.u32.u64 %0, t; }" : "=r"(a) : "l"(p));
    return a;
}
__device__ __forceinline__ void cp16(uint32_t saddr, const void* g) {
    asm volatile("cp.async.cg.shared.global [%0], [%1], 16;" :: "r"(saddr), "l"(g));
}
__device__ __forceinline__ void cp_commit() {
    asm volatile("cp.async.commit_group;" ::: "memory");
}
template <int N>
__device__ __forceinline__ void cp_wait() {
    asm volatile("cp.async.wait_group %0;" :: "n"(N) : "memory");
}
__device__ __forceinline__ void ldsm4(uint32_t* r, uint32_t a) {
    asm volatile("ldmatrix.sync.aligned.m8n8.x4.shared.b16 {%0,%1,%2,%3}, [%4];"
                 : "=r"(r[0]), "=r"(r[1]), "=r"(r[2]), "=r"(r[3]) : "r"(a));
}
__device__ __forceinline__ void ldsm4t(uint32_t* r, uint32_t a) {
    asm volatile("ldmatrix.sync.aligned.m8n8.x4.trans.shared.b16 {%0,%1,%2,%3}, [%4];"
                 : "=r"(r[0]), "=r"(r[1]), "=r"(r[2]), "=r"(r[3]) : "r"(a));
}
__device__ __forceinline__ void mma16816(float* c, const uint32_t* a, const uint32_t* b) {
    asm volatile(
        "mma.sync.aligned.m16n8k16.row.col.f32.bf16.bf16.f32 "
        "{%0,%1,%2,%3}, {%4,%5,%6,%7}, {%8,%9}, {%0,%1,%2,%3};"
        : "+f"(c[0]), "+f"(c[1]), "+f"(c[2]), "+f"(c[3])
        : "r"(a[0]), "r"(a[1]), "r"(a[2]), "r"(a[3]), "r"(b[0]), "r"(b[1]));
}
__device__ __forceinline__ void split2(float x, float y, uint32_t& hi, uint32_t& lo) {
    __nv_bfloat162 h2 = __float22bfloat162_rn(make_float2(x, y));
    float hx = __bfloat162float(h2.x), hy = __bfloat162float(h2.y);
    __nv_bfloat162 l2 = __float22bfloat162_rn(make_float2(x - hx, y - hy));
    hi = *(uint32_t*)&h2;
    lo = *(uint32_t*)&l2;
}

// ---------------- prep kernels ----------------
__global__ void split_plain(const float* __restrict__ in,
                            __nv_bfloat16* __restrict__ hi,
                            __nv_bfloat16* __restrict__ lo, size_t n4)
{
    size_t i = (size_t)blockIdx.x * blockDim.x + threadIdx.x;
    size_t stride = (size_t)gridDim.x * blockDim.x;
    for (; i < n4; i += stride) {
        float4 x = ((const float4*)in)[i];
        __nv_bfloat16 h0 = __float2bfloat16(x.x), h1 = __float2bfloat16(x.y);
        __nv_bfloat16 h2 = __float2bfloat16(x.z), h3 = __float2bfloat16(x.w);
        __nv_bfloat16 l0 = __float2bfloat16(x.x - __bfloat162float(h0));
        __nv_bfloat16 l1 = __float2bfloat16(x.y - __bfloat162float(h1));
        __nv_bfloat16 l2 = __float2bfloat16(x.z - __bfloat162float(h2));
        __nv_bfloat16 l3 = __float2bfloat16(x.w - __bfloat162float(h3));
        ((__nv_bfloat162*)hi)[i * 2 + 0] = __nv_bfloat162(h0, h1);
        ((__nv_bfloat162*)hi)[i * 2 + 1] = __nv_bfloat162(h2, h3);
        ((__nv_bfloat162*)lo)[i * 2 + 0] = __nv_bfloat162(l0, l1);
        ((__nv_bfloat162*)lo)[i * 2 + 1] = __nv_bfloat162(l2, l3);
    }
}

__global__ void transpose_split(const float* __restrict__ in,
                                __nv_bfloat16* __restrict__ hi,
                                __nv_bfloat16* __restrict__ lo, int R, int C)
{
    __shared__ float t[32][33];
    const int bx = blockIdx.x * 32, by = blockIdx.y * 32;
    const int tx = threadIdx.x, ty = threadIdx.y;
#pragma unroll
    for (int j = 0; j < 4; ++j)
        t[ty + 8 * j][tx] = in[(size_t)(by + ty + 8 * j) * C + bx + tx];
    __syncthreads();
#pragma unroll
    for (int j = 0; j < 4; ++j) {
        float v = t[tx][ty + 8 * j];
        __nv_bfloat16 h = __float2bfloat16(v);
        __nv_bfloat16 l = __float2bfloat16(v - __bfloat162float(h));
        size_t o = (size_t)(bx + ty + 8 * j) * R + by + tx;
        hi[o] = h;
        lo[o] = l;
    }
}

// ---------------- HMMA bf16x3 GEMM: C[M,N] = A[M,K] @ B[N,K]^T ----------------
// CTA tile 256x128, BK=32, 16 warps (8m x 2n), warp tile 32x64.
// 3-stage cp.async pipeline; MMAs grouped by term for accumulator ILP.
#define BM 256
#define BN 128
#define BK 32
#define ROWB 80
#define A_TILEB (256 * ROWB)
#define B_TILEB (128 * ROWB)
#define STAGEB (2 * A_TILEB + 2 * B_TILEB)  // 61440
#define GSMEM (3 * STAGEB)                   // 184320

__global__ __launch_bounds__(512)
void gemm_hmma(const __nv_bfloat16* __restrict__ Ahi, const __nv_bfloat16* __restrict__ Alo,
               const __nv_bfloat16* __restrict__ Bhi, const __nv_bfloat16* __restrict__ Blo,
               float* __restrict__ C, int M, int N, int K, int mode)
{
    extern __shared__ char smraw[];
    const uint32_t sb = smem_u32(smraw);

    const int tid = threadIdx.x, wid = tid >> 5, lane = tid & 31;
    const int bm = blockIdx.y * BM, bn = blockIdx.x * BN;
    const int wm = wid >> 1, wn = wid & 1;

    const __nv_bfloat16* Ahi_p = Ahi + (size_t)bm * K;
    const __nv_bfloat16* Alo_p = Alo + (size_t)bm * K;
    const __nv_bfloat16* Bhi_p = Bhi + (size_t)bn * K;
    const __nv_bfloat16* Blo_p = Blo + (size_t)bn * K;

    const int nk = K / BK;

    auto stage_load = [&](int s, int kc) {
        const uint32_t base = sb + s * STAGEB;
        const size_t kofs = (size_t)kc * BK;
#pragma unroll
        for (int i = 0; i < 2; ++i) {
            const int v = tid + i * 512;
            const int row = v >> 2, c = v & 3;
            const uint32_t off = row * ROWB + c * 16;
            const size_t go = (size_t)row * K + kofs + c * 8;
            cp16(base + off,            Ahi_p + go);
            cp16(base + A_TILEB + off,  Alo_p + go);
        }
        {
            const int row = tid >> 2, c = tid & 3;
            const uint32_t off = row * ROWB + c * 16;
            const size_t go = (size_t)row * K + kofs + c * 8;
            cp16(base + 2 * A_TILEB + off,            Bhi_p + go);
            cp16(base + 2 * A_TILEB + B_TILEB + off,  Blo_p + go);
        }
    };

    float acc[16][4];
#pragma unroll
    for (int i = 0; i < 16; ++i)
#pragma unroll
        for (int j = 0; j < 4; ++j) acc[i][j] = 0.f;

    stage_load(0, 0); cp_commit();
    stage_load(1, 1); cp_commit();
    cp_wait<1>();
    __syncthreads();

    for (int c = 0; c < nk; ++c) {
        const int s = c - (c / 3) * 3;
        if (c + 2 < nk) {
            const int s2 = (c + 2) - ((c + 2) / 3) * 3;
            stage_load(s2, c + 2);
            cp_commit();
        }

        const uint32_t Ah = sb + s * STAGEB;
        const uint32_t Al = Ah + A_TILEB;
        const uint32_t Bh = Ah + 2 * A_TILEB;
        const uint32_t Bl = Bh + B_TILEB;

#pragma unroll
        for (int ks = 0; ks < 2; ++ks) {
            uint32_t ah[2][4], al[2][4];
#pragma unroll
            for (int mt = 0; mt < 2; ++mt) {
                const uint32_t ro = (uint32_t)(wm * 32 + mt * 16 + (lane & 15)) * ROWB
                                  + ks * 32 + (lane >> 4) * 16;
                ldsm4(ah[mt], Ah + ro);
                ldsm4(al[mt], Al + ro);
            }
            // process bt in pairs; within a pair issue term-grouped MMAs:
            // 8 independent accumulators per group -> no C RAW stalls.
#pragma unroll
            for (int bp = 0; bp < 2; ++bp) {
                uint32_t bh[2][4], bl[2][4];
#pragma unroll
                for (int j = 0; j < 2; ++j) {
                    const int bt = bp * 2 + j;
                    const uint32_t ro = (uint32_t)(wn * 64 + bt * 16 + (lane & 15)) * ROWB
                                      + ks * 32 + (lane >> 4) * 16;
                    ldsm4(bh[j], Bh + ro);
                    ldsm4(bl[j], Bl + ro);
                }
                // hi * hi
#pragma unroll
                for (int j = 0; j < 2; ++j) {
                    const uint32_t b0[2] = { bh[j][0], bh[j][2] };
                    const uint32_t b1[2] = { bh[j][1], bh[j][3] };
                    const int ai = (bp * 2 + j) * 2;
#pragma unroll
                    for (int mt = 0; mt < 2; ++mt) {
                        mma16816(acc[mt * 8 + ai + 0], ah[mt], b0);
                        mma16816(acc[mt * 8 + ai + 1], ah[mt], b1);
                    }
                }
                // hi * lo
#pragma unroll
                for (int j = 0; j < 2; ++j) {
                    const uint32_t b0[2] = { bl[j][0], bl[j][2] };
                    const uint32_t b1[2] = { bl[j][1], bl[j][3] };
                    const int ai = (bp * 2 + j) * 2;
#pragma unroll
                    for (int mt = 0; mt < 2; ++mt) {
                        mma16816(acc[mt * 8 + ai + 0], ah[mt], b0);
                        mma16816(acc[mt * 8 + ai + 1], ah[mt], b1);
                    }
                }
                // lo * hi
#pragma unroll
                for (int j = 0; j < 2; ++j) {
                    const uint32_t b0[2] = { bh[j][0], bh[j][2] };
                    const uint32_t b1[2] = { bh[j][1], bh[j][3] };
                    const int ai = (bp * 2 + j) * 2;
#pragma unroll
                    for (int mt = 0; mt < 2; ++mt) {
                        mma16816(acc[mt * 8 + ai + 0], al[mt], b0);
                        mma16816(acc[mt * 8 + ai + 1], al[mt], b1);
                    }
                }
            }
        }

        if (c + 2 < nk) cp_wait<1>(); else cp_wait<0>();
        __syncthreads();
    }

    const int group = bn >> 11;

    // ---- fused clamp+RMSNorm for q,k (mode 1) ----
    float* ssm = (float*)smraw;
    if (mode && group < 2) {
        float ssp[2][2] = { {0.f, 0.f}, {0.f, 0.f} };
#pragma unroll
        for (int mt = 0; mt < 2; ++mt)
#pragma unroll
            for (int bt = 0; bt < 4; ++bt)
#pragma unroll
                for (int half = 0; half < 2; ++half) {
                    float* a = acc[mt * 8 + bt * 2 + half];
#pragma unroll
                    for (int q = 0; q < 4; ++q) {
                        float v = fminf(fmaxf(a[q], -FP16MAX), FP16MAX);
                        a[q] = v;
                        ssp[mt][q >> 1] += v * v;
                    }
                }
#pragma unroll
        for (int mt = 0; mt < 2; ++mt)
#pragma unroll
            for (int hh = 0; hh < 2; ++hh) {
                float s0 = ssp[mt][hh];
                s0 += __shfl_xor_sync(0xffffffffu, s0, 1);
                s0 += __shfl_xor_sync(0xffffffffu, s0, 2);
                if ((lane & 3) == 0) {
                    const int row = wm * 32 + mt * 16 + (lane >> 2) + hh * 8;
                    ssm[wn * 256 + row] = s0;
                }
            }
        __syncthreads();
        const float post = (group == 0) ? ATTN_SCALE : 1.0f;
#pragma unroll
        for (int mt = 0; mt < 2; ++mt)
#pragma unroll
            for (int hh = 0; hh < 2; ++hh) {
                const int row = wm * 32 + mt * 16 + (lane >> 2) + hh * 8;
                const float tot = ssm[row] + ssm[256 + row];
                const float sc = rsqrtf(tot * (1.0f / 128.0f) + RMS_EPS) * post;
#pragma unroll
                for (int bt = 0; bt < 4; ++bt)
#pragma unroll
                    for (int half = 0; half < 2; ++half) {
                        acc[mt * 8 + bt * 2 + half][hh * 2 + 0] *= sc;
                        acc[mt * 8 + bt * 2 + half][hh * 2 + 1] *= sc;
                    }
            }
    }

    if (mode) {
        const int hh = (bn >> 7) & 15;
        __nv_bfloat16* dsth = (group == 0) ? g_qh : (group == 1) ? g_kh : g_vh;
        __nv_bfloat16* dstl = (group == 0) ? g_ql : (group == 1) ? g_kl : g_vl;
#pragma unroll
        for (int mt = 0; mt < 2; ++mt)
#pragma unroll
            for (int bt = 0; bt < 4; ++bt)
#pragma unroll
                for (int half = 0; half < 2; ++half) {
                    const int d = wn * 64 + bt * 16 + half * 8 + (lane & 3) * 2;
                    float* a = acc[mt * 8 + bt * 2 + half];
#pragma unroll
                    for (int rr = 0; rr < 2; ++rr) {
                        const int row = bm + wm * 32 + mt * 16 + (lane >> 2) + rr * 8;
                        const int bb = row >> 11, s = row & 2047;
                        const size_t idx = ((size_t)(bb * HEADS + hh) * SEQ + s) * HD + d;
                        const float x = a[rr * 2 + 0], y = a[rr * 2 + 1];
                        if (group == 3) {
                            *(float2*)(g_gate + idx) = make_float2(x, y);
                        } else {
                            uint32_t hi, lo;
                            split2(x, y, hi, lo);
                            *(uint32_t*)(dsth + idx) = hi;
                            *(uint32_t*)(dstl + idx) = lo;
                        }
                    }
                }
    } else {
#pragma unroll
        for (int mt = 0; mt < 2; ++mt)
#pragma unroll
            for (int bt = 0; bt < 4; ++bt)
#pragma unroll
                for (int half = 0; half < 2; ++half) {
                    const int col = bn + wn * 64 + bt * 16 + half * 8 + (lane & 3) * 2;
                    const int r0 = bm + wm * 32 + mt * 16 + (lane >> 2);
                    float* a = acc[mt * 8 + bt * 2 + half];
                    *(float2*)(C + (size_t)r0 * N + col)       = make_float2(a[0], a[1]);
                    *(float2*)(C + (size_t)(r0 + 8) * N + col) = make_float2(a[2], a[3]);
                }
    }
}

// ---------------- HMMA bf16x3 flash attention ----------------
#define AROWB 272
#define QROWS 256
#define QT (QROWS * AROWB)
#define KVR 32
#define KVB (KVR * AROWB)
#define STG (4 * KVB)
#define ATTN_SMEM (2 * QT + 2 * STG)     // 208896

__global__ __launch_bounds__(512, 1)
void attn_hmma()
{
    extern __shared__ char smraw[];
    const uint32_t sb = smem_u32(smraw);

    const int tid = threadIdx.x, w = tid >> 5, lane = tid & 31;
    const int qt = blockIdx.x, h = blockIdx.y, b = blockIdx.z;
    const size_t hb = ((size_t)b * HEADS + h) * SEQ;

    const __nv_bfloat16* Qh_g = g_qh + (hb + qt * QROWS) * HD;
    const __nv_bfloat16* Ql_g = g_ql + (hb + qt * QROWS) * HD;
    const __nv_bfloat16* Kh_g = g_kh + hb * HD;
    const __nv_bfloat16* Kl_g = g_kl + hb * HD;
    const __nv_bfloat16* Vh_g = g_vh + hb * HD;
    const __nv_bfloat16* Vl_g = g_vl + hb * HD;

    auto loadKV = [&](int s, int kt) {
        const uint32_t base = sb + 2 * QT + s * STG;
        const size_t kv0 = (size_t)kt * KVR;
        const int row = tid >> 4, c = tid & 15;
        const uint32_t so = base + row * AROWB + c * 16;
        const size_t go = (kv0 + row) * HD + c * 8;
        cp16(so,           Kh_g + go);
        cp16(so + KVB,     Kl_g + go);
        cp16(so + 2 * KVB, Vh_g + go);
        cp16(so + 3 * KVB, Vl_g + go);
    };

#pragma unroll
    for (int i = 0; i < 8; ++i) {
        const int v = tid + i * 512;
        const int row = v >> 4, c = v & 15;
        const uint32_t so = row * AROWB + c * 16;
        const size_t go = (size_t)row * HD + c * 8;
        cp16(sb + so,      Qh_g + go);
        cp16(sb + QT + so, Ql_g + go);
    }
    loadKV(0, 0); cp_commit();
    loadKV(1, 1); cp_commit();
    cp_wait<1>();
    __syncthreads();

    float oacc[16][4];
#pragma unroll
    for (int i = 0; i < 16; ++i)
#pragma unroll
        for (int j = 0; j < 4; ++j) oacc[i][j] = 0.f;
    float m0 = -INFINITY, m1 = -INFINITY, l0 = 0.f, l1 = 0.f;

    const int nkt = SEQ / KVR;   // 64
    for (int c = 0; c < nkt; ++c) {
        const int s = c & 1;
        const uint32_t kbase = sb + 2 * QT + s * STG;

        // ---- S = Q @ K^T (bf16x3), term-grouped for acc ILP ----
        float sacc[4][4];
#pragma unroll
        for (int i = 0; i < 4; ++i)
#pragma unroll
            for (int j = 0; j < 4; ++j) sacc[i][j] = 0.f;

#pragma unroll
        for (int kt = 0; kt < 8; ++kt) {
            uint32_t ah[4], al[4];
            const uint32_t qo = (uint32_t)(w * 16 + (lane & 15)) * AROWB
                              + kt * 32 + (lane >> 4) * 16;
            ldsm4(ah, sb + qo);
            ldsm4(al, sb + QT + qo);
            uint32_t bh[2][4], bl[2][4];
#pragma unroll
            for (int g = 0; g < 2; ++g) {
                const uint32_t ko = kbase + (uint32_t)(g * 16 + (lane & 15)) * AROWB
                                  + kt * 32 + (lane >> 4) * 16;
                ldsm4(bh[g], ko);
                ldsm4(bl[g], ko + KVB);
            }
            // hh (4 indep accs), then hl, then lh
#pragma unroll
            for (int g = 0; g < 2; ++g) {
                const uint32_t b0[2] = { bh[g][0], bh[g][2] }, b1[2] = { bh[g][1], bh[g][3] };
                mma16816(sacc[2 * g + 0], ah, b0);
                mma16816(sacc[2 * g + 1], ah, b1);
            }
#pragma unroll
            for (int g = 0; g < 2; ++g) {
                const uint32_t b0[2] = { bl[g][0], bl[g][2] }, b1[2] = { bl[g][1], bl[g][3] };
                mma16816(sacc[2 * g + 0], ah, b0);
                mma16816(sacc[2 * g + 1], ah, b1);
            }
#pragma unroll
            for (int g = 0; g < 2; ++g) {
                const uint32_t b0[2] = { bh[g][0], bh[g][2] }, b1[2] = { bh[g][1], bh[g][3] };
                mma16816(sacc[2 * g + 0], al, b0);
                mma16816(sacc[2 * g + 1], al, b1);
            }
        }

        // ---- online softmax ----
        float mx0 = -INFINITY, mx1 = -INFINITY;
#pragma unroll
        for (int j = 0; j < 4; ++j) {
            mx0 = fmaxf(mx0, fmaxf(sacc[j][0], sacc[j][1]));
            mx1 = fmaxf(mx1, fmaxf(sacc[j][2], sacc[j][3]));
        }
        mx0 = fmaxf(mx0, __shfl_xor_sync(0xffffffffu, mx0, 1));
        mx0 = fmaxf(mx0, __shfl_xor_sync(0xffffffffu, mx0, 2));
        mx1 = fmaxf(mx1, __shfl_xor_sync(0xffffffffu, mx1, 1));
        mx1 = fmaxf(mx1, __shfl_xor_sync(0xffffffffu, mx1, 2));
        const float mn0 = fmaxf(m0, mx0), mn1 = fmaxf(m1, mx1);
        const float corr0 = __expf(m0 - mn0), corr1 = __expf(m1 - mn1);
        m0 = mn0; m1 = mn1;
        float rs0 = 0.f, rs1 = 0.f;
#pragma unroll
        for (int j = 0; j < 4; ++j) {
            sacc[j][0] = __expf(sacc[j][0] - mn0);
            sacc[j][1] = __expf(sacc[j][1] - mn0);
            sacc[j][2] = __expf(sacc[j][2] - mn1);
            sacc[j][3] = __expf(sacc[j][3] - mn1);
            rs0 += sacc[j][0] + sacc[j][1];
            rs1 += sacc[j][2] + sacc[j][3];
        }
        rs0 += __shfl_xor_sync(0xffffffffu, rs0, 1);
        rs0 += __shfl_xor_sync(0xffffffffu, rs0, 2);
        rs1 += __shfl_xor_sync(0xffffffffu, rs1, 1);
        rs1 += __shfl_xor_sync(0xffffffffu, rs1, 2);
        l0 = l0 * corr0 + rs0;
        l1 = l1 * corr1 + rs1;
#pragma unroll
        for (int n = 0; n < 16; ++n) {
            oacc[n][0] *= corr0; oacc[n][1] *= corr0;
            oacc[n][2] *= corr1; oacc[n][3] *= corr1;
        }

        // ---- P (C-frag) -> A-frag hi/lo ----
        uint32_t pah[2][4], pal[2][4];
#pragma unroll
        for (int kc = 0; kc < 2; ++kc) {
            split2(sacc[2 * kc][0],     sacc[2 * kc][1],     pah[kc][0], pal[kc][0]);
            split2(sacc[2 * kc][2],     sacc[2 * kc][3],     pah[kc][1], pal[kc][1]);
            split2(sacc[2 * kc + 1][0], sacc[2 * kc + 1][1], pah[kc][2], pal[kc][2]);
            split2(sacc[2 * kc + 1][2], sacc[2 * kc + 1][3], pah[kc][3], pal[kc][3]);
        }

        // ---- O += P @ V, g2 processed in pairs, term-grouped ----
#pragma unroll
        for (int kc = 0; kc < 2; ++kc) {
#pragma unroll
            for (int gp = 0; gp < 4; ++gp) {
                uint32_t vh[2][4], vl[2][4];
#pragma unroll
                for (int j = 0; j < 2; ++j) {
                    const int g2 = gp * 2 + j;
                    const uint32_t vo = kbase + 2 * KVB
                                      + (uint32_t)(kc * 16 + (lane & 15)) * AROWB
                                      + (g2 * 16 + (lane >> 4) * 8) * 2;
                    ldsm4t(vh[j], vo);
                    ldsm4t(vl[j], vo + KVB);
                }
                // hh (4 indep accs)
#pragma unroll
                for (int j = 0; j < 2; ++j) {
                    const int g2 = gp * 2 + j;
                    const uint32_t b0[2] = { vh[j][0], vh[j][1] }, b1[2] = { vh[j][2], vh[j][3] };
                    mma16816(oacc[2 * g2 + 0], pah[kc], b0);
                    mma16816(oacc[2 * g2 + 1], pah[kc], b1);
                }
                // hl
#pragma unroll
                for (int j = 0; j < 2; ++j) {
                    const int g2 = gp * 2 + j;
                    const uint32_t b0[2] = { vl[j][0], vl[j][1] }, b1[2] = { vl[j][2], vl[j][3] };
                    mma16816(oacc[2 * g2 + 0], pah[kc], b0);
                    mma16816(oacc[2 * g2 + 1], pah[kc], b1);
                }
                // lh
#pragma unroll
                for (int j = 0; j < 2; ++j) {
                    const int g2 = gp * 2 + j;
                    const uint32_t b0[2] = { vh[j][0], vh[j][1] }, b1[2] = { vh[j][2], vh[j][3] };
                    mma16816(oacc[2 * g2 + 0], pal[kc], b0);
                    mma16816(oacc[2 * g2 + 1], pal[kc], b1);
                }
            }
        }

        __syncthreads();
        if (c + 2 < nkt) {
            loadKV(s, c + 2);
            cp_commit();
            cp_wait<1>();
        } else {
            cp_wait<0>();
        }
        __syncthreads();
    }

    const float inv0 = 1.0f / l0, inv1 = 1.0f / l1;
    const int r0 = w * 16 + (lane >> 2);
#pragma unroll
    for (int n = 0; n < 16; ++n) {
        const int d = n * 8 + (lane & 3) * 2;
#pragma unroll
        for (int rr = 0; rr < 2; ++rr) {
            const int qrow = qt * QROWS + r0 + rr * 8;
            const float inv = rr ? inv1 : inv0;
            const float2 gv = *(const float2*)(g_gate + (hb + qrow) * HD + d);
            const float sg0 = 1.0f / (1.0f + __expf(-gv.x));
            const float sg1 = 1.0f / (1.0f + __expf(-gv.y));
            const float x = sg0 * oacc[n][rr * 2 + 0] * inv;
            const float y = sg1 * oacc[n][rr * 2 + 1] * inv;
            uint32_t hi, lo;
            split2(x, y, hi, lo);
            const size_t o = (size_t)(b * SEQ + qrow) * DMODEL + h * HD + d;
            *(uint32_t*)(g_th + o) = hi;
            *(uint32_t*)(g_tl + o) = lo;
        }
    }
}

// ---------------------------------------------------------------------------
extern "C" void kernel_launch(void* const* d_in, const int* in_sizes, int n_in,
                              void* d_out, int out_size)
{
    const float* hidden = (const float*)d_in[0];
    const float* W_in   = (const float*)d_in[1];
    const float* W_out  = (const float*)d_in[2];
    float* out = (float*)d_out;

    __nv_bfloat16 *ahi, *alo, *winh, *winl, *woh, *wol, *th, *tl;
    cudaGetSymbolAddress((void**)&ahi,  g_ahi);
    cudaGetSymbolAddress((void**)&alo,  g_alo);
    cudaGetSymbolAddress((void**)&winh, g_winh);
    cudaGetSymbolAddress((void**)&winl, g_winl);
    cudaGetSymbolAddress((void**)&woh,  g_woh);
    cudaGetSymbolAddress((void**)&wol,  g_wol);
    cudaGetSymbolAddress((void**)&th,   g_th);
    cudaGetSymbolAddress((void**)&tl,   g_tl);

    cudaFuncSetAttribute(gemm_hmma,
                         cudaFuncAttributeMaxDynamicSharedMemorySize, GSMEM);
    cudaFuncSetAttribute(attn_hmma,
                         cudaFuncAttributeMaxDynamicSharedMemorySize, ATTN_SMEM);

    split_plain<<<1024, 256>>>(hidden, ahi, alo, (size_t)ROWS * DMODEL / 4);
    transpose_split<<<dim3(NPROJ / 32, DMODEL / 32), dim3(32, 8)>>>(W_in, winh, winl,
                                                                    DMODEL, NPROJ);
    transpose_split<<<dim3(DMODEL / 32, DMODEL / 32), dim3(32, 8)>>>(W_out, woh, wol,
                                                                     DMODEL, DMODEL);

    gemm_hmma<<<dim3(NPROJ / BN, ROWS / BM), 512, GSMEM>>>(
        ahi, alo, winh, winl, nullptr, ROWS, NPROJ, DMODEL, 1);

    attn_hmma<<<dim3(SEQ / QROWS, HEADS, NB), 512, ATTN_SMEM>>>();

    gemm_hmma<<<dim3(DMODEL / BN, ROWS / BM), 512, GSMEM>>>(
        th, tl, woh, wol, out, ROWS, DMODEL, DMODEL, 0);
}

// round 8
// speedup vs baseline: 1.3967x; 1.3967x over previous
#include <cuda_runtime.h>
#include <cuda_fp16.h>
#include <math.h>
#include <stdint.h>

// Problem constants
#define ROWS   4096          // B*S
#define DMODEL 2048
#define NPROJ  8192          // 4*DMODEL
#define HEADS  16
#define HD     128
#define SEQ    2048
#define NB     2
#define FP16MAX 65504.0f
#define RMS_EPS 1e-5f
#define ATTN_SCALE 0.08838834764831845f

// ---------------- scratch (allocation-free) ----------------
#define HSD ((size_t)NB * HEADS * SEQ * HD)
__device__ __half g_qh[HSD], g_ql[HSD];     // q split hi/lo
__device__ __half g_kh[HSD];                 // k single fp16
__device__ __half g_vh[HSD];                 // v single fp16
__device__ float  g_gate[HSD];
__device__ __half g_ahi [(size_t)ROWS * DMODEL];   // hidden hi
__device__ __half g_alo [(size_t)ROWS * DMODEL];   // hidden lo
__device__ __half g_win [(size_t)NPROJ * DMODEL];  // W_in^T single fp16 [N,K]
__device__ __half g_woh [(size_t)DMODEL * DMODEL]; // W_out^T hi [N,K]
__device__ __half g_wol [(size_t)DMODEL * DMODEL]; // W_out^T lo
__device__ __half g_th  [(size_t)ROWS * DMODEL];   // attn out hi
__device__ __half g_tl  [(size_t)ROWS * DMODEL];   // attn out lo

// ---------------- PTX helpers (sm_80-portable only) ----------------
__device__ __forceinline__ uint32_t smem_u32(const void* p) {
    uint32_t a;
    asm("{ .reg .u64 t; cvta.to.shared.u64 t, %1; cvt.u32.u64 %0, t; }" : "=r"(a) : "l"(p));
    return a;
}
__device__ __forceinline__ void cp16(uint32_t saddr, const void* g) {
    asm volatile("cp.async.cg.shared.global [%0], [%1], 16;" :: "r"(saddr), "l"(g));
}
__device__ __forceinline__ void cp_commit() {
    asm volatile("cp.async.commit_group;" ::: "memory");
}
template <int N>
__device__ __forceinline__ void cp_wait() {
    asm volatile("cp.async.wait_group %0;" :: "n"(N) : "memory");
}
__device__ __forceinline__ void ldsm4(uint32_t* r, uint32_t a) {
    asm volatile("ldmatrix.sync.aligned.m8n8.x4.shared.b16 {%0,%1,%2,%3}, [%4];"
                 : "=r"(r[0]), "=r"(r[1]), "=r"(r[2]), "=r"(r[3]) : "r"(a));
}
__device__ __forceinline__ void ldsm4t(uint32_t* r, uint32_t a) {
    asm volatile("ldmatrix.sync.aligned.m8n8.x4.trans.shared.b16 {%0,%1,%2,%3}, [%4];"
                 : "=r"(r[0]), "=r"(r[1]), "=r"(r[2]), "=r"(r[3]) : "r"(a));
}
__device__ __forceinline__ void mma16816(float* c, const uint32_t* a, const uint32_t* b) {
    asm volatile(
        "mma.sync.aligned.m16n8k16.row.col.f32.f16.f16.f32 "
        "{%0,%1,%2,%3}, {%4,%5,%6,%7}, {%8,%9}, {%0,%1,%2,%3};"
        : "+f"(c[0]), "+f"(c[1]), "+f"(c[2]), "+f"(c[3])
        : "r"(a[0]), "r"(a[1]), "r"(a[2]), "r"(a[3]), "r"(b[0]), "r"(b[1]));
}
// fp32 pair -> fp16 hi + fp16 lo (packed half2 words)
__device__ __forceinline__ void splith2(float x, float y, uint32_t& hi, uint32_t& lo) {
    __half2 h2 = __floats2half2_rn(x, y);
    float hx = __low2float(h2), hy = __high2float(h2);
    __half2 l2 = __floats2half2_rn(x - hx, y - hy);
    hi = *(uint32_t*)&h2;
    lo = *(uint32_t*)&l2;
}
__device__ __forceinline__ uint32_t roundh2(float x, float y) {
    __half2 h2 = __floats2half2_rn(x, y);
    return *(uint32_t*)&h2;
}

// ---------------- prep kernels ----------------
__global__ void split_plain(const float* __restrict__ in,
                            __half* __restrict__ hi,
                            __half* __restrict__ lo, size_t n4)
{
    size_t i = (size_t)blockIdx.x * blockDim.x + threadIdx.x;
    size_t stride = (size_t)gridDim.x * blockDim.x;
    for (; i < n4; i += stride) {
        float4 x = ((const float4*)in)[i];
        uint32_t h0, l0, h1, l1;
        splith2(x.x, x.y, h0, l0);
        splith2(x.z, x.w, h1, l1);
        ((uint32_t*)hi)[i * 2 + 0] = h0;
        ((uint32_t*)hi)[i * 2 + 1] = h1;
        ((uint32_t*)lo)[i * 2 + 0] = l0;
        ((uint32_t*)lo)[i * 2 + 1] = l1;
    }
}

// transpose + round: in [R,C] fp32 -> out [C,R] single fp16
__global__ void transpose_round(const float* __restrict__ in,
                                __half* __restrict__ hi, int R, int C)
{
    __shared__ float t[32][33];
    const int bx = blockIdx.x * 32, by = blockIdx.y * 32;
    const int tx = threadIdx.x, ty = threadIdx.y;
#pragma unroll
    for (int j = 0; j < 4; ++j)
        t[ty + 8 * j][tx] = in[(size_t)(by + ty + 8 * j) * C + bx + tx];
    __syncthreads();
#pragma unroll
    for (int j = 0; j < 4; ++j) {
        float v = t[tx][ty + 8 * j];
        hi[(size_t)(bx + ty + 8 * j) * R + by + tx] = __float2half_rn(v);
    }
}

// transpose + split: in [R,C] fp32 -> out [C,R] fp16 hi/lo
__global__ void transpose_split(const float* __restrict__ in,
                                __half* __restrict__ hi,
                                __half* __restrict__ lo, int R, int C)
{
    __shared__ float t[32][33];
    const int bx = blockIdx.x * 32, by = blockIdx.y * 32;
    const int tx = threadIdx.x, ty = threadIdx.y;
#pragma unroll
    for (int j = 0; j < 4; ++j)
        t[ty + 8 * j][tx] = in[(size_t)(by + ty + 8 * j) * C + bx + tx];
    __syncthreads();
#pragma unroll
    for (int j = 0; j < 4; ++j) {
        float v = t[tx][ty + 8 * j];
        __half h = __float2half_rn(v);
        __half l = __float2half_rn(v - __half2float(h));
        size_t o = (size_t)(bx + ty + 8 * j) * R + by + tx;
        hi[o] = h;
        lo[o] = l;
    }
}

// ---------------- HMMA fp16 GEMM: C[M,N] = A[M,K] @ B[N,K]^T ----------------
// A split hi/lo (2 terms); B optionally split (3rd term, BSPLIT=1).
// 128x128 block tile, BK=32, 8 warps (4m x 2n), 2-stage cp.async (R5 config).
#define BM 128
#define BN 128
#define BK 32
#define ROWB 80
#define TILEB (128 * ROWB)          // 10240 per matrix
#define STAGEB (4 * TILEB)          // reserve 4 slots (max case)
#define GSMEM (2 * STAGEB)          // 81920

template <int BSPLIT>
__global__ __launch_bounds__(256)
void gemm_hmma(const __half* __restrict__ Ahi, const __half* __restrict__ Alo,
               const __half* __restrict__ Bhi, const __half* __restrict__ Blo,
               float* __restrict__ C, int M, int N, int K, int mode)
{
    extern __shared__ char smraw[];
    const uint32_t sb = smem_u32(smraw);

    const int tid = threadIdx.x, wid = tid >> 5, lane = tid & 31;
    const int bm = blockIdx.y * BM, bn = blockIdx.x * BN;
    const int wm = wid >> 1, wn = wid & 1;

    const __half* gsrc[4] = {
        Ahi + (size_t)bm * K, Alo + (size_t)bm * K,
        Bhi + (size_t)bn * K, BSPLIT ? (Blo + (size_t)bn * K) : (Bhi + (size_t)bn * K) };

    const int nk = K / BK;
    const int nmat = 3 + BSPLIT;

    auto stage_load = [&](int s, int kc) {
        const uint32_t base = sb + s * STAGEB;
        const size_t kofs = (size_t)kc * BK;
#pragma unroll
        for (int b = 0; b < nmat; ++b) {
#pragma unroll
            for (int i = 0; i < 2; ++i) {
                const int v = tid + i * 256;
                const int row = v >> 2, c = v & 3;
                cp16(base + b * TILEB + row * ROWB + c * 16,
                     gsrc[b] + (size_t)row * K + kofs + c * 8);
            }
        }
    };

    float acc[16][4];
#pragma unroll
    for (int i = 0; i < 16; ++i)
#pragma unroll
        for (int j = 0; j < 4; ++j) acc[i][j] = 0.f;

    stage_load(0, 0); cp_commit();
    stage_load(1, 1); cp_commit();
    cp_wait<1>();
    __syncthreads();

    for (int c = 0; c < nk; ++c) {
        const int s = c & 1;
        const uint32_t Ah = sb + s * STAGEB;
        const uint32_t Al = Ah + TILEB;
        const uint32_t Bh = Ah + 2 * TILEB;
        const uint32_t Bl = Ah + 3 * TILEB;

#pragma unroll
        for (int ks = 0; ks < 2; ++ks) {
            uint32_t ah[2][4], al[2][4];
#pragma unroll
            for (int mt = 0; mt < 2; ++mt) {
                const uint32_t ro = (uint32_t)(wm * 32 + mt * 16 + (lane & 15)) * ROWB
                                  + ks * 32 + (lane >> 4) * 16;
                ldsm4(ah[mt], Ah + ro);
                ldsm4(al[mt], Al + ro);
            }
#pragma unroll
            for (int bt = 0; bt < 4; ++bt) {
                const uint32_t ro = (uint32_t)(wn * 64 + bt * 16 + (lane & 15)) * ROWB
                                  + ks * 32 + (lane >> 4) * 16;
                uint32_t bh[4];
                ldsm4(bh, Bh + ro);
                const uint32_t b0h[2] = { bh[0], bh[2] }, b1h[2] = { bh[1], bh[3] };
#pragma unroll
                for (int mt = 0; mt < 2; ++mt) {
                    mma16816(acc[mt * 8 + bt * 2 + 0], ah[mt], b0h);
                    mma16816(acc[mt * 8 + bt * 2 + 1], ah[mt], b1h);
                    mma16816(acc[mt * 8 + bt * 2 + 0], al[mt], b0h);
                    mma16816(acc[mt * 8 + bt * 2 + 1], al[mt], b1h);
                }
                if (BSPLIT) {
                    uint32_t bl[4];
                    ldsm4(bl, Bl + ro);
                    const uint32_t b0l[2] = { bl[0], bl[2] }, b1l[2] = { bl[1], bl[3] };
#pragma unroll
                    for (int mt = 0; mt < 2; ++mt) {
                        mma16816(acc[mt * 8 + bt * 2 + 0], ah[mt], b0l);
                        mma16816(acc[mt * 8 + bt * 2 + 1], ah[mt], b1l);
                    }
                }
            }
        }

        __syncthreads();
        if (c + 2 < nk) {
            stage_load(s, c + 2);
            cp_commit();
            cp_wait<1>();
        } else {
            cp_wait<0>();
        }
        __syncthreads();
    }

    const int group = bn >> 11;       // 0=q 1=k 2=v 3=g (mode 1 only)

    // ---- fused clamp+RMSNorm for q,k (mode 1) ----
    float* ssm = (float*)smraw;       // [2][128]
    if (mode && group < 2) {
        float ssp[2][2] = { {0.f, 0.f}, {0.f, 0.f} };
#pragma unroll
        for (int mt = 0; mt < 2; ++mt)
#pragma unroll
            for (int bt = 0; bt < 4; ++bt)
#pragma unroll
                for (int half = 0; half < 2; ++half) {
                    float* a = acc[mt * 8 + bt * 2 + half];
#pragma unroll
                    for (int q = 0; q < 4; ++q) {
                        float v = fminf(fmaxf(a[q], -FP16MAX), FP16MAX);
                        a[q] = v;
                        ssp[mt][q >> 1] += v * v;
                    }
                }
#pragma unroll
        for (int mt = 0; mt < 2; ++mt)
#pragma unroll
            for (int hh = 0; hh < 2; ++hh) {
                float s0 = ssp[mt][hh];
                s0 += __shfl_xor_sync(0xffffffffu, s0, 1);
                s0 += __shfl_xor_sync(0xffffffffu, s0, 2);
                if ((lane & 3) == 0) {
                    const int row = wm * 32 + mt * 16 + (lane >> 2) + hh * 8;
                    ssm[wn * 128 + row] = s0;
                }
            }
        __syncthreads();
        const float post = (group == 0) ? ATTN_SCALE : 1.0f;
#pragma unroll
        for (int mt = 0; mt < 2; ++mt)
#pragma unroll
            for (int hh = 0; hh < 2; ++hh) {
                const int row = wm * 32 + mt * 16 + (lane >> 2) + hh * 8;
                const float tot = ssm[row] + ssm[128 + row];
                const float sc = rsqrtf(tot * (1.0f / 128.0f) + RMS_EPS) * post;
#pragma unroll
                for (int bt = 0; bt < 4; ++bt)
#pragma unroll
                    for (int half = 0; half < 2; ++half) {
                        acc[mt * 8 + bt * 2 + half][hh * 2 + 0] *= sc;
                        acc[mt * 8 + bt * 2 + half][hh * 2 + 1] *= sc;
                    }
            }
    }

    if (mode) {
        // q split hi/lo; k,v single fp16; gate fp32. Layout [b][h][s][d].
        const int hh = (bn >> 7) & 15;
#pragma unroll
        for (int mt = 0; mt < 2; ++mt)
#pragma unroll
            for (int bt = 0; bt < 4; ++bt)
#pragma unroll
                for (int half = 0; half < 2; ++half) {
                    const int d = wn * 64 + bt * 16 + half * 8 + (lane & 3) * 2;
                    float* a = acc[mt * 8 + bt * 2 + half];
#pragma unroll
                    for (int rr = 0; rr < 2; ++rr) {
                        const int row = bm + wm * 32 + mt * 16 + (lane >> 2) + rr * 8;
                        const int bb = row >> 11, s = row & 2047;
                        const size_t idx = ((size_t)(bb * HEADS + hh) * SEQ + s) * HD + d;
                        const float x = a[rr * 2 + 0], y = a[rr * 2 + 1];
                        if (group == 0) {
                            uint32_t hi, lo;
                            splith2(x, y, hi, lo);
                            *(uint32_t*)(g_qh + idx) = hi;
                            *(uint32_t*)(g_ql + idx) = lo;
                        } else if (group == 1) {
                            *(uint32_t*)(g_kh + idx) = roundh2(x, y);
                        } else if (group == 2) {
                            *(uint32_t*)(g_vh + idx) = roundh2(x, y);
                        } else {
                            *(float2*)(g_gate + idx) = make_float2(x, y);
                        }
                    }
                }
    } else {
#pragma unroll
        for (int mt = 0; mt < 2; ++mt)
#pragma unroll
            for (int bt = 0; bt < 4; ++bt)
#pragma unroll
                for (int half = 0; half < 2; ++half) {
                    const int col = bn + wn * 64 + bt * 16 + half * 8 + (lane & 3) * 2;
                    const int r0 = bm + wm * 32 + mt * 16 + (lane >> 2);
                    float* a = acc[mt * 8 + bt * 2 + half];
                    *(float2*)(C + (size_t)r0 * N + col)       = make_float2(a[0], a[1]);
                    *(float2*)(C + (size_t)(r0 + 8) * N + col) = make_float2(a[2], a[3]);
                }
    }
}

// ---------------- HMMA fp16x2 flash attention ----------------
// 512 threads = 16 warps, each warp 16 q rows -> 256 q rows per CTA.
// q split hi/lo; K,V single fp16. KV chunks of 32, double buffered.
#define AROWB 272                        // 128 fp16 = 256 B + 16 pad
#define QROWS 256
#define QT (QROWS * AROWB)               // 69632
#define KVR 32
#define KVB (KVR * AROWB)                // 8704
#define STG (2 * KVB)                    // k + v = 17408
#define ATTN_SMEM (2 * QT + 2 * STG)     // 174080

__global__ __launch_bounds__(512, 1)
void attn_hmma()
{
    extern __shared__ char smraw[];
    const uint32_t sb = smem_u32(smraw);

    const int tid = threadIdx.x, w = tid >> 5, lane = tid & 31;
    const int qt = blockIdx.x, h = blockIdx.y, b = blockIdx.z;
    const size_t hb = ((size_t)b * HEADS + h) * SEQ;

    const __half* Qh_g = g_qh + (hb + qt * QROWS) * HD;
    const __half* Ql_g = g_ql + (hb + qt * QROWS) * HD;
    const __half* Kh_g = g_kh + hb * HD;
    const __half* Vh_g = g_vh + hb * HD;

    auto loadKV = [&](int s, int kt) {
        const uint32_t base = sb + 2 * QT + s * STG;
        const size_t kv0 = (size_t)kt * KVR;
        const int row = tid >> 4, c = tid & 15;
        const uint32_t so = base + row * AROWB + c * 16;
        const size_t go = (kv0 + row) * HD + c * 8;
        cp16(so,       Kh_g + go);
        cp16(so + KVB, Vh_g + go);
    };

#pragma unroll
    for (int i = 0; i < 8; ++i) {
        const int v = tid + i * 512;
        const int row = v >> 4, c = v & 15;
        const uint32_t so = row * AROWB + c * 16;
        const size_t go = (size_t)row * HD + c * 8;
        cp16(sb + so,      Qh_g + go);
        cp16(sb + QT + so, Ql_g + go);
    }
    loadKV(0, 0); cp_commit();
    loadKV(1, 1); cp_commit();
    cp_wait<1>();
    __syncthreads();

    float oacc[16][4];
#pragma unroll
    for (int i = 0; i < 16; ++i)
#pragma unroll
        for (int j = 0; j < 4; ++j) oacc[i][j] = 0.f;
    float m0 = -INFINITY, m1 = -INFINITY, l0 = 0.f, l1 = 0.f;

    const int nkt = SEQ / KVR;   // 64
    for (int c = 0; c < nkt; ++c) {
        const int s = c & 1;
        const uint32_t kbase = sb + 2 * QT + s * STG;

        // ---- S = Q @ K^T : (qh + ql) * k ----
        float sacc[4][4];
#pragma unroll
        for (int i = 0; i < 4; ++i)
#pragma unroll
            for (int j = 0; j < 4; ++j) sacc[i][j] = 0.f;

#pragma unroll
        for (int kt = 0; kt < 8; ++kt) {
            uint32_t ah[4], al[4];
            const uint32_t qo = (uint32_t)(w * 16 + (lane & 15)) * AROWB
                              + kt * 32 + (lane >> 4) * 16;
            ldsm4(ah, sb + qo);
            ldsm4(al, sb + QT + qo);
#pragma unroll
            for (int g = 0; g < 2; ++g) {
                const uint32_t ko = kbase + (uint32_t)(g * 16 + (lane & 15)) * AROWB
                                  + kt * 32 + (lane >> 4) * 16;
                uint32_t bh[4];
                ldsm4(bh, ko);
                const uint32_t b0[2] = { bh[0], bh[2] }, b1[2] = { bh[1], bh[3] };
                mma16816(sacc[2 * g + 0], ah, b0);
                mma16816(sacc[2 * g + 1], ah, b1);
                mma16816(sacc[2 * g + 0], al, b0);
                mma16816(sacc[2 * g + 1], al, b1);
            }
        }

        // ---- online softmax ----
        float mx0 = -INFINITY, mx1 = -INFINITY;
#pragma unroll
        for (int j = 0; j < 4; ++j) {
            mx0 = fmaxf(mx0, fmaxf(sacc[j][0], sacc[j][1]));
            mx1 = fmaxf(mx1, fmaxf(sacc[j][2], sacc[j][3]));
        }
        mx0 = fmaxf(mx0, __shfl_xor_sync(0xffffffffu, mx0, 1));
        mx0 = fmaxf(mx0, __shfl_xor_sync(0xffffffffu, mx0, 2));
        mx1 = fmaxf(mx1, __shfl_xor_sync(0xffffffffu, mx1, 1));
        mx1 = fmaxf(mx1, __shfl_xor_sync(0xffffffffu, mx1, 2));
        const float mn0 = fmaxf(m0, mx0), mn1 = fmaxf(m1, mx1);
        const float corr0 = __expf(m0 - mn0), corr1 = __expf(m1 - mn1);
        m0 = mn0; m1 = mn1;
        float rs0 = 0.f, rs1 = 0.f;
#pragma unroll
        for (int j = 0; j < 4; ++j) {
            sacc[j][0] = __expf(sacc[j][0] - mn0);
            sacc[j][1] = __expf(sacc[j][1] - mn0);
            sacc[j][2] = __expf(sacc[j][2] - mn1);
            sacc[j][3] = __expf(sacc[j][3] - mn1);
            rs0 += sacc[j][0] + sacc[j][1];
            rs1 += sacc[j][2] + sacc[j][3];
        }
        rs0 += __shfl_xor_sync(0xffffffffu, rs0, 1);
        rs0 += __shfl_xor_sync(0xffffffffu, rs0, 2);
        rs1 += __shfl_xor_sync(0xffffffffu, rs1, 1);
        rs1 += __shfl_xor_sync(0xffffffffu, rs1, 2);
        l0 = l0 * corr0 + rs0;
        l1 = l1 * corr1 + rs1;
#pragma unroll
        for (int n = 0; n < 16; ++n) {
            oacc[n][0] *= corr0; oacc[n][1] *= corr0;
            oacc[n][2] *= corr1; oacc[n][3] *= corr1;
        }

        // ---- P (C-frag) -> A-frag hi/lo fp16, in registers ----
        uint32_t pah[2][4], pal[2][4];
#pragma unroll
        for (int kc = 0; kc < 2; ++kc) {
            splith2(sacc[2 * kc][0],     sacc[2 * kc][1],     pah[kc][0], pal[kc][0]);
            splith2(sacc[2 * kc][2],     sacc[2 * kc][3],     pah[kc][1], pal[kc][1]);
            splith2(sacc[2 * kc + 1][0], sacc[2 * kc + 1][1], pah[kc][2], pal[kc][2]);
            splith2(sacc[2 * kc + 1][2], sacc[2 * kc + 1][3], pah[kc][3], pal[kc][3]);
        }

        // ---- O += P @ V : (Ph + Pl) * v ----
#pragma unroll
        for (int kc = 0; kc < 2; ++kc) {
#pragma unroll
            for (int g2 = 0; g2 < 8; ++g2) {
                const uint32_t vo = kbase + KVB
                                  + (uint32_t)(kc * 16 + (lane & 15)) * AROWB
                                  + (g2 * 16 + (lane >> 4) * 8) * 2;
                uint32_t vh[4];
                ldsm4t(vh, vo);
                const uint32_t b0[2] = { vh[0], vh[1] }, b1[2] = { vh[2], vh[3] };
                mma16816(oacc[2 * g2 + 0], pah[kc], b0);
                mma16816(oacc[2 * g2 + 1], pah[kc], b1);
                mma16816(oacc[2 * g2 + 0], pal[kc], b0);
                mma16816(oacc[2 * g2 + 1], pal[kc], b1);
            }
        }

        __syncthreads();
        if (c + 2 < nkt) {
            loadKV(s, c + 2);
            cp_commit();
            cp_wait<1>();
        } else {
            cp_wait<0>();
        }
        __syncthreads();
    }

    // ---- epilogue: O/l, sigmoid gate, split hi/lo fp16 for GEMM2 ----
    const float inv0 = 1.0f / l0, inv1 = 1.0f / l1;
    const int r0 = w * 16 + (lane >> 2);
#pragma unroll
    for (int n = 0; n < 16; ++n) {
        const int d = n * 8 + (lane & 3) * 2;
#pragma unroll
        for (int rr = 0; rr < 2; ++rr) {
            const int qrow = qt * QROWS + r0 + rr * 8;
            const float inv = rr ? inv1 : inv0;
            const float2 gv = *(const float2*)(g_gate + (hb + qrow) * HD + d);
            const float sg0 = 1.0f / (1.0f + __expf(-gv.x));
            const float sg1 = 1.0f / (1.0f + __expf(-gv.y));
            const float x = sg0 * oacc[n][rr * 2 + 0] * inv;
            const float y = sg1 * oacc[n][rr * 2 + 1] * inv;
            uint32_t hi, lo;
            splith2(x, y, hi, lo);
            const size_t o = (size_t)(b * SEQ + qrow) * DMODEL + h * HD + d;
            *(uint32_t*)(g_th + o) = hi;
            *(uint32_t*)(g_tl + o) = lo;
        }
    }
}

// ---------------------------------------------------------------------------
extern "C" void kernel_launch(void* const* d_in, const int* in_sizes, int n_in,
                              void* d_out, int out_size)
{
    const float* hidden = (const float*)d_in[0];
    const float* W_in   = (const float*)d_in[1];
    const float* W_out  = (const float*)d_in[2];
    float* out = (float*)d_out;

    __half *ahi, *alo, *win, *woh, *wol, *th, *tl;
    cudaGetSymbolAddress((void**)&ahi, g_ahi);
    cudaGetSymbolAddress((void**)&alo, g_alo);
    cudaGetSymbolAddress((void**)&win, g_win);
    cudaGetSymbolAddress((void**)&woh, g_woh);
    cudaGetSymbolAddress((void**)&wol, g_wol);
    cudaGetSymbolAddress((void**)&th,  g_th);
    cudaGetSymbolAddress((void**)&tl,  g_tl);

    cudaFuncSetAttribute(gemm_hmma<0>,
                         cudaFuncAttributeMaxDynamicSharedMemorySize, GSMEM);
    cudaFuncSetAttribute(gemm_hmma<1>,
                         cudaFuncAttributeMaxDynamicSharedMemorySize, GSMEM);
    cudaFuncSetAttribute(attn_hmma,
                         cudaFuncAttributeMaxDynamicSharedMemorySize, ATTN_SMEM);

    // prep: split hidden (fp16 hi/lo); W_in -> single fp16 T; W_out -> split fp16 T
    split_plain<<<1024, 256>>>(hidden, ahi, alo, (size_t)ROWS * DMODEL / 4);
    transpose_round<<<dim3(NPROJ / 32, DMODEL / 32), dim3(32, 8)>>>(W_in, win,
                                                                    DMODEL, NPROJ);
    transpose_split<<<dim3(DMODEL / 32, DMODEL / 32), dim3(32, 8)>>>(W_out, woh, wol,
                                                                     DMODEL, DMODEL);

    // 1) proj GEMM (2-term fp16) -> q split + rmsnorm/scale, k/v single, gate fp32
    gemm_hmma<0><<<dim3(NPROJ / BN, ROWS / BM), 256, GSMEM>>>(
        ahi, alo, win, nullptr, nullptr, ROWS, NPROJ, DMODEL, 1);

    // 2) fp16x2 flash attention + sigmoid gate -> g_th/g_tl
    attn_hmma<<<dim3(SEQ / QROWS, HEADS, NB), 512, ATTN_SMEM>>>();

    // 3) out = att @ W_out (3-term fp16: A split + B split)
    gemm_hmma<1><<<dim3(DMODEL / BN, ROWS / BM), 256, GSMEM>>>(
        th, tl, woh, wol, out, ROWS, DMODEL, DMODEL, 0);
}

// round 9
// speedup vs baseline: 1.7380x; 1.2443x over previous
#include <cuda_runtime.h>
#include <cuda_fp16.h>
#include <math.h>
#include <stdint.h>

// Problem constants
#define ROWS   4096          // B*S
#define DMODEL 2048
#define NPROJ  8192          // 4*DMODEL
#define HEADS  16
#define HD     128
#define SEQ    2048
#define NB     2
#define FP16MAX 65504.0f
#define RMS_EPS 1e-5f
#define ATTN_SCALE 0.08838834764831845f

// ---------------- scratch (allocation-free) ----------------
#define HSD ((size_t)NB * HEADS * SEQ * HD)
__device__ __half g_qh[HSD], g_ql[HSD];     // q split hi/lo
__device__ __half g_kh[HSD];                 // k single fp16
__device__ __half g_vh[HSD];                 // v single fp16
__device__ float  g_gate[HSD];
__device__ __half g_ah  [(size_t)ROWS * DMODEL];   // hidden rounded fp16
__device__ __half g_win [(size_t)NPROJ * DMODEL];  // W_in^T single fp16 [N,K]
__device__ __half g_woh [(size_t)DMODEL * DMODEL]; // W_out^T hi [N,K]
__device__ __half g_wol [(size_t)DMODEL * DMODEL]; // W_out^T lo
__device__ __half g_th  [(size_t)ROWS * DMODEL];   // attn out hi
__device__ __half g_tl  [(size_t)ROWS * DMODEL];   // attn out lo

// ---------------- PTX helpers (sm_80-portable only) ----------------
__device__ __forceinline__ uint32_t smem_u32(const void* p) {
    uint32_t a;
    asm("{ .reg .u64 t; cvta.to.shared.u64 t, %1; cvt.u32.u64 %0, t; }" : "=r"(a) : "l"(p));
    return a;
}
__device__ __forceinline__ void cp16(uint32_t saddr, const void* g) {
    asm volatile("cp.async.cg.shared.global [%0], [%1], 16;" :: "r"(saddr), "l"(g));
}
__device__ __forceinline__ void cp_commit() {
    asm volatile("cp.async.commit_group;" ::: "memory");
}
template <int N>
__device__ __forceinline__ void cp_wait() {
    asm volatile("cp.async.wait_group %0;" :: "n"(N) : "memory");
}
__device__ __forceinline__ void ldsm4(uint32_t* r, uint32_t a) {
    asm volatile("ldmatrix.sync.aligned.m8n8.x4.shared.b16 {%0,%1,%2,%3}, [%4];"
                 : "=r"(r[0]), "=r"(r[1]), "=r"(r[2]), "=r"(r[3]) : "r"(a));
}
__device__ __forceinline__ void ldsm4t(uint32_t* r, uint32_t a) {
    asm volatile("ldmatrix.sync.aligned.m8n8.x4.trans.shared.b16 {%0,%1,%2,%3}, [%4];"
                 : "=r"(r[0]), "=r"(r[1]), "=r"(r[2]), "=r"(r[3]) : "r"(a));
}
__device__ __forceinline__ void mma16816(float* c, const uint32_t* a, const uint32_t* b) {
    asm volatile(
        "mma.sync.aligned.m16n8k16.row.col.f32.f16.f16.f32 "
        "{%0,%1,%2,%3}, {%4,%5,%6,%7}, {%8,%9}, {%0,%1,%2,%3};"
        : "+f"(c[0]), "+f"(c[1]), "+f"(c[2]), "+f"(c[3])
        : "r"(a[0]), "r"(a[1]), "r"(a[2]), "r"(a[3]), "r"(b[0]), "r"(b[1]));
}
__device__ __forceinline__ void splith2(float x, float y, uint32_t& hi, uint32_t& lo) {
    __half2 h2 = __floats2half2_rn(x, y);
    float hx = __low2float(h2), hy = __high2float(h2);
    __half2 l2 = __floats2half2_rn(x - hx, y - hy);
    hi = *(uint32_t*)&h2;
    lo = *(uint32_t*)&l2;
}
__device__ __forceinline__ uint32_t roundh2(float x, float y) {
    __half2 h2 = __floats2half2_rn(x, y);
    return *(uint32_t*)&h2;
}

// ---------------- prep kernels ----------------
__global__ void round_plain(const float* __restrict__ in,
                            __half* __restrict__ hi, size_t n4)
{
    size_t i = (size_t)blockIdx.x * blockDim.x + threadIdx.x;
    size_t stride = (size_t)gridDim.x * blockDim.x;
    for (; i < n4; i += stride) {
        float4 x = ((const float4*)in)[i];
        ((uint32_t*)hi)[i * 2 + 0] = roundh2(x.x, x.y);
        ((uint32_t*)hi)[i * 2 + 1] = roundh2(x.z, x.w);
    }
}

__global__ void transpose_round(const float* __restrict__ in,
                                __half* __restrict__ hi, int R, int C)
{
    __shared__ float t[32][33];
    const int bx = blockIdx.x * 32, by = blockIdx.y * 32;
    const int tx = threadIdx.x, ty = threadIdx.y;
#pragma unroll
    for (int j = 0; j < 4; ++j)
        t[ty + 8 * j][tx] = in[(size_t)(by + ty + 8 * j) * C + bx + tx];
    __syncthreads();
#pragma unroll
    for (int j = 0; j < 4; ++j) {
        float v = t[tx][ty + 8 * j];
        hi[(size_t)(bx + ty + 8 * j) * R + by + tx] = __float2half_rn(v);
    }
}

__global__ void transpose_split(const float* __restrict__ in,
                                __half* __restrict__ hi,
                                __half* __restrict__ lo, int R, int C)
{
    __shared__ float t[32][33];
    const int bx = blockIdx.x * 32, by = blockIdx.y * 32;
    const int tx = threadIdx.x, ty = threadIdx.y;
#pragma unroll
    for (int j = 0; j < 4; ++j)
        t[ty + 8 * j][tx] = in[(size_t)(by + ty + 8 * j) * C + bx + tx];
    __syncthreads();
#pragma unroll
    for (int j = 0; j < 4; ++j) {
        float v = t[tx][ty + 8 * j];
        __half h = __float2half_rn(v);
        __half l = __float2half_rn(v - __half2float(h));
        size_t o = (size_t)(bx + ty + 8 * j) * R + by + tx;
        hi[o] = h;
        lo[o] = l;
    }
}

// ---------------- HMMA fp16 GEMM: C[M,N] = A[M,K] @ B[N,K]^T ----------------
// TERMS=1: round(A)*round(B).  TERMS=3: (Ahi+Alo)*Bhi + Ahi*Blo.
// 128x128 block tile, BK=32, 8 warps (4m x 2n), 2-stage cp.async.
#define BM 128
#define BN 128
#define BK 32
#define ROWB 80
#define TILEB (128 * ROWB)          // 10240 per matrix
#define STAGEB (4 * TILEB)          // fixed 4 slots
#define GSMEM (2 * STAGEB)          // 81920

template <int TERMS>
__global__ __launch_bounds__(256)
void gemm_hmma(const __half* __restrict__ Ahi, const __half* __restrict__ Alo,
               const __half* __restrict__ Bhi, const __half* __restrict__ Blo,
               float* __restrict__ C, int M, int N, int K, int mode)
{
    extern __shared__ char smraw[];
    const uint32_t sb = smem_u32(smraw);

    const int tid = threadIdx.x, wid = tid >> 5, lane = tid & 31;
    const int bm = blockIdx.y * BM, bn = blockIdx.x * BN;
    const int wm = wid >> 1, wn = wid & 1;

    const __half* Ahi_p = Ahi + (size_t)bm * K;
    const __half* Alo_p = (TERMS >= 2) ? (Alo + (size_t)bm * K) : nullptr;
    const __half* Bhi_p = Bhi + (size_t)bn * K;
    const __half* Blo_p = (TERMS >= 3) ? (Blo + (size_t)bn * K) : nullptr;

    const int nk = K / BK;

    auto load_mat = [&](uint32_t dst, const __half* src, size_t kofs) {
#pragma unroll
        for (int i = 0; i < 2; ++i) {
            const int v = tid + i * 256;
            const int row = v >> 2, c = v & 3;
            cp16(dst + row * ROWB + c * 16, src + (size_t)row * K + kofs + c * 8);
        }
    };
    auto stage_load = [&](int s, int kc) {
        const uint32_t base = sb + s * STAGEB;
        const size_t kofs = (size_t)kc * BK;
        load_mat(base,             Ahi_p, kofs);
        if (TERMS >= 2) load_mat(base + TILEB, Alo_p, kofs);
        load_mat(base + 2 * TILEB, Bhi_p, kofs);
        if (TERMS >= 3) load_mat(base + 3 * TILEB, Blo_p, kofs);
    };

    float acc[16][4];
#pragma unroll
    for (int i = 0; i < 16; ++i)
#pragma unroll
        for (int j = 0; j < 4; ++j) acc[i][j] = 0.f;

    stage_load(0, 0); cp_commit();
    stage_load(1, 1); cp_commit();
    cp_wait<1>();
    __syncthreads();

    for (int c = 0; c < nk; ++c) {
        const int s = c & 1;
        const uint32_t Ah = sb + s * STAGEB;
        const uint32_t Al = Ah + TILEB;
        const uint32_t Bh = Ah + 2 * TILEB;
        const uint32_t Bl = Ah + 3 * TILEB;

#pragma unroll
        for (int ks = 0; ks < 2; ++ks) {
            uint32_t ah[2][4], al[2][4];
#pragma unroll
            for (int mt = 0; mt < 2; ++mt) {
                const uint32_t ro = (uint32_t)(wm * 32 + mt * 16 + (lane & 15)) * ROWB
                                  + ks * 32 + (lane >> 4) * 16;
                ldsm4(ah[mt], Ah + ro);
                if (TERMS >= 2) ldsm4(al[mt], Al + ro);
            }
#pragma unroll
            for (int bt = 0; bt < 4; ++bt) {
                const uint32_t ro = (uint32_t)(wn * 64 + bt * 16 + (lane & 15)) * ROWB
                                  + ks * 32 + (lane >> 4) * 16;
                uint32_t bh[4];
                ldsm4(bh, Bh + ro);
                const uint32_t b0h[2] = { bh[0], bh[2] }, b1h[2] = { bh[1], bh[3] };
#pragma unroll
                for (int mt = 0; mt < 2; ++mt) {
                    mma16816(acc[mt * 8 + bt * 2 + 0], ah[mt], b0h);
                    mma16816(acc[mt * 8 + bt * 2 + 1], ah[mt], b1h);
                    if (TERMS >= 2) {
                        mma16816(acc[mt * 8 + bt * 2 + 0], al[mt], b0h);
                        mma16816(acc[mt * 8 + bt * 2 + 1], al[mt], b1h);
                    }
                }
                if (TERMS >= 3) {
                    uint32_t bl[4];
                    ldsm4(bl, Bl + ro);
                    const uint32_t b0l[2] = { bl[0], bl[2] }, b1l[2] = { bl[1], bl[3] };
#pragma unroll
                    for (int mt = 0; mt < 2; ++mt) {
                        mma16816(acc[mt * 8 + bt * 2 + 0], ah[mt], b0l);
                        mma16816(acc[mt * 8 + bt * 2 + 1], ah[mt], b1l);
                    }
                }
            }
        }

        __syncthreads();
        if (c + 2 < nk) {
            stage_load(s, c + 2);
            cp_commit();
            cp_wait<1>();
        } else {
            cp_wait<0>();
        }
        __syncthreads();
    }

    const int group = bn >> 11;       // 0=q 1=k 2=v 3=g (mode 1 only)

    // ---- fused clamp+RMSNorm for q,k (mode 1) ----
    float* ssm = (float*)smraw;
    if (mode && group < 2) {
        float ssp[2][2] = { {0.f, 0.f}, {0.f, 0.f} };
#pragma unroll
        for (int mt = 0; mt < 2; ++mt)
#pragma unroll
            for (int bt = 0; bt < 4; ++bt)
#pragma unroll
                for (int half = 0; half < 2; ++half) {
                    float* a = acc[mt * 8 + bt * 2 + half];
#pragma unroll
                    for (int q = 0; q < 4; ++q) {
                        float v = fminf(fmaxf(a[q], -FP16MAX), FP16MAX);
                        a[q] = v;
                        ssp[mt][q >> 1] += v * v;
                    }
                }
#pragma unroll
        for (int mt = 0; mt < 2; ++mt)
#pragma unroll
            for (int hh = 0; hh < 2; ++hh) {
                float s0 = ssp[mt][hh];
                s0 += __shfl_xor_sync(0xffffffffu, s0, 1);
                s0 += __shfl_xor_sync(0xffffffffu, s0, 2);
                if ((lane & 3) == 0) {
                    const int row = wm * 32 + mt * 16 + (lane >> 2) + hh * 8;
                    ssm[wn * 128 + row] = s0;
                }
            }
        __syncthreads();
        const float post = (group == 0) ? ATTN_SCALE : 1.0f;
#pragma unroll
        for (int mt = 0; mt < 2; ++mt)
#pragma unroll
            for (int hh = 0; hh < 2; ++hh) {
                const int row = wm * 32 + mt * 16 + (lane >> 2) + hh * 8;
                const float tot = ssm[row] + ssm[128 + row];
                const float sc = rsqrtf(tot * (1.0f / 128.0f) + RMS_EPS) * post;
#pragma unroll
                for (int bt = 0; bt < 4; ++bt)
#pragma unroll
                    for (int half = 0; half < 2; ++half) {
                        acc[mt * 8 + bt * 2 + half][hh * 2 + 0] *= sc;
                        acc[mt * 8 + bt * 2 + half][hh * 2 + 1] *= sc;
                    }
            }
    }

    if (mode) {
        // q split hi/lo; k,v single fp16; gate fp32. Layout [b][h][s][d].
        const int hh = (bn >> 7) & 15;
#pragma unroll
        for (int mt = 0; mt < 2; ++mt)
#pragma unroll
            for (int bt = 0; bt < 4; ++bt)
#pragma unroll
                for (int half = 0; half < 2; ++half) {
                    const int d = wn * 64 + bt * 16 + half * 8 + (lane & 3) * 2;
                    float* a = acc[mt * 8 + bt * 2 + half];
#pragma unroll
                    for (int rr = 0; rr < 2; ++rr) {
                        const int row = bm + wm * 32 + mt * 16 + (lane >> 2) + rr * 8;
                        const int bb = row >> 11, s = row & 2047;
                        const size_t idx = ((size_t)(bb * HEADS + hh) * SEQ + s) * HD + d;
                        const float x = a[rr * 2 + 0], y = a[rr * 2 + 1];
                        if (group == 0) {
                            uint32_t hi, lo;
                            splith2(x, y, hi, lo);
                            *(uint32_t*)(g_qh + idx) = hi;
                            *(uint32_t*)(g_ql + idx) = lo;
                        } else if (group == 1) {
                            *(uint32_t*)(g_kh + idx) = roundh2(x, y);
                        } else if (group == 2) {
                            *(uint32_t*)(g_vh + idx) = roundh2(x, y);
                        } else {
                            *(float2*)(g_gate + idx) = make_float2(x, y);
                        }
                    }
                }
    } else {
#pragma unroll
        for (int mt = 0; mt < 2; ++mt)
#pragma unroll
            for (int bt = 0; bt < 4; ++bt)
#pragma unroll
                for (int half = 0; half < 2; ++half) {
                    const int col = bn + wn * 64 + bt * 16 + half * 8 + (lane & 3) * 2;
                    const int r0 = bm + wm * 32 + mt * 16 + (lane >> 2);
                    float* a = acc[mt * 8 + bt * 2 + half];
                    *(float2*)(C + (size_t)r0 * N + col)       = make_float2(a[0], a[1]);
                    *(float2*)(C + (size_t)(r0 + 8) * N + col) = make_float2(a[2], a[3]);
                }
    }
}

// ---------------- HMMA fp16x2 flash attention (unchanged from R8) ----------------
#define AROWB 272
#define QROWS 256
#define QT (QROWS * AROWB)
#define KVR 32
#define KVB (KVR * AROWB)
#define STG (2 * KVB)
#define ATTN_SMEM (2 * QT + 2 * STG)     // 174080

__global__ __launch_bounds__(512, 1)
void attn_hmma()
{
    extern __shared__ char smraw[];
    const uint32_t sb = smem_u32(smraw);

    const int tid = threadIdx.x, w = tid >> 5, lane = tid & 31;
    const int qt = blockIdx.x, h = blockIdx.y, b = blockIdx.z;
    const size_t hb = ((size_t)b * HEADS + h) * SEQ;

    const __half* Qh_g = g_qh + (hb + qt * QROWS) * HD;
    const __half* Ql_g = g_ql + (hb + qt * QROWS) * HD;
    const __half* Kh_g = g_kh + hb * HD;
    const __half* Vh_g = g_vh + hb * HD;

    auto loadKV = [&](int s, int kt) {
        const uint32_t base = sb + 2 * QT + s * STG;
        const size_t kv0 = (size_t)kt * KVR;
        const int row = tid >> 4, c = tid & 15;
        const uint32_t so = base + row * AROWB + c * 16;
        const size_t go = (kv0 + row) * HD + c * 8;
        cp16(so,       Kh_g + go);
        cp16(so + KVB, Vh_g + go);
    };

#pragma unroll
    for (int i = 0; i < 8; ++i) {
        const int v = tid + i * 512;
        const int row = v >> 4, c = v & 15;
        const uint32_t so = row * AROWB + c * 16;
        const size_t go = (size_t)row * HD + c * 8;
        cp16(sb + so,      Qh_g + go);
        cp16(sb + QT + so, Ql_g + go);
    }
    loadKV(0, 0); cp_commit();
    loadKV(1, 1); cp_commit();
    cp_wait<1>();
    __syncthreads();

    float oacc[16][4];
#pragma unroll
    for (int i = 0; i < 16; ++i)
#pragma unroll
        for (int j = 0; j < 4; ++j) oacc[i][j] = 0.f;
    float m0 = -INFINITY, m1 = -INFINITY, l0 = 0.f, l1 = 0.f;

    const int nkt = SEQ / KVR;   // 64
    for (int c = 0; c < nkt; ++c) {
        const int s = c & 1;
        const uint32_t kbase = sb + 2 * QT + s * STG;

        float sacc[4][4];
#pragma unroll
        for (int i = 0; i < 4; ++i)
#pragma unroll
            for (int j = 0; j < 4; ++j) sacc[i][j] = 0.f;

#pragma unroll
        for (int kt = 0; kt < 8; ++kt) {
            uint32_t ah[4], al[4];
            const uint32_t qo = (uint32_t)(w * 16 + (lane & 15)) * AROWB
                              + kt * 32 + (lane >> 4) * 16;
            ldsm4(ah, sb + qo);
            ldsm4(al, sb + QT + qo);
#pragma unroll
            for (int g = 0; g < 2; ++g) {
                const uint32_t ko = kbase + (uint32_t)(g * 16 + (lane & 15)) * AROWB
                                  + kt * 32 + (lane >> 4) * 16;
                uint32_t bh[4];
                ldsm4(bh, ko);
                const uint32_t b0[2] = { bh[0], bh[2] }, b1[2] = { bh[1], bh[3] };
                mma16816(sacc[2 * g + 0], ah, b0);
                mma16816(sacc[2 * g + 1], ah, b1);
                mma16816(sacc[2 * g + 0], al, b0);
                mma16816(sacc[2 * g + 1], al, b1);
            }
        }

        float mx0 = -INFINITY, mx1 = -INFINITY;
#pragma unroll
        for (int j = 0; j < 4; ++j) {
            mx0 = fmaxf(mx0, fmaxf(sacc[j][0], sacc[j][1]));
            mx1 = fmaxf(mx1, fmaxf(sacc[j][2], sacc[j][3]));
        }
        mx0 = fmaxf(mx0, __shfl_xor_sync(0xffffffffu, mx0, 1));
        mx0 = fmaxf(mx0, __shfl_xor_sync(0xffffffffu, mx0, 2));
        mx1 = fmaxf(mx1, __shfl_xor_sync(0xffffffffu, mx1, 1));
        mx1 = fmaxf(mx1, __shfl_xor_sync(0xffffffffu, mx1, 2));
        const float mn0 = fmaxf(m0, mx0), mn1 = fmaxf(m1, mx1);
        const float corr0 = __expf(m0 - mn0), corr1 = __expf(m1 - mn1);
        m0 = mn0; m1 = mn1;
        float rs0 = 0.f, rs1 = 0.f;
#pragma unroll
        for (int j = 0; j < 4; ++j) {
            sacc[j][0] = __expf(sacc[j][0] - mn0);
            sacc[j][1] = __expf(sacc[j][1] - mn0);
            sacc[j][2] = __expf(sacc[j][2] - mn1);
            sacc[j][3] = __expf(sacc[j][3] - mn1);
            rs0 += sacc[j][0] + sacc[j][1];
            rs1 += sacc[j][2] + sacc[j][3];
        }
        rs0 += __shfl_xor_sync(0xffffffffu, rs0, 1);
        rs0 += __shfl_xor_sync(0xffffffffu, rs0, 2);
        rs1 += __shfl_xor_sync(0xffffffffu, rs1, 1);
        rs1 += __shfl_xor_sync(0xffffffffu, rs1, 2);
        l0 = l0 * corr0 + rs0;
        l1 = l1 * corr1 + rs1;
#pragma unroll
        for (int n = 0; n < 16; ++n) {
            oacc[n][0] *= corr0; oacc[n][1] *= corr0;
            oacc[n][2] *= corr1; oacc[n][3] *= corr1;
        }

        uint32_t pah[2][4], pal[2][4];
#pragma unroll
        for (int kc = 0; kc < 2; ++kc) {
            splith2(sacc[2 * kc][0],     sacc[2 * kc][1],     pah[kc][0], pal[kc][0]);
            splith2(sacc[2 * kc][2],     sacc[2 * kc][3],     pah[kc][1], pal[kc][1]);
            splith2(sacc[2 * kc + 1][0], sacc[2 * kc + 1][1], pah[kc][2], pal[kc][2]);
            splith2(sacc[2 * kc + 1][2], sacc[2 * kc + 1][3], pah[kc][3], pal[kc][3]);
        }

#pragma unroll
        for (int kc = 0; kc < 2; ++kc) {
#pragma unroll
            for (int g2 = 0; g2 < 8; ++g2) {
                const uint32_t vo = kbase + KVB
                                  + (uint32_t)(kc * 16 + (lane & 15)) * AROWB
                                  + (g2 * 16 + (lane >> 4) * 8) * 2;
                uint32_t vh[4];
                ldsm4t(vh, vo);
                const uint32_t b0[2] = { vh[0], vh[1] }, b1[2] = { vh[2], vh[3] };
                mma16816(oacc[2 * g2 + 0], pah[kc], b0);
                mma16816(oacc[2 * g2 + 1], pah[kc], b1);
                mma16816(oacc[2 * g2 + 0], pal[kc], b0);
                mma16816(oacc[2 * g2 + 1], pal[kc], b1);
            }
        }

        __syncthreads();
        if (c + 2 < nkt) {
            loadKV(s, c + 2);
            cp_commit();
            cp_wait<1>();
        } else {
            cp_wait<0>();
        }
        __syncthreads();
    }

    const float inv0 = 1.0f / l0, inv1 = 1.0f / l1;
    const int r0 = w * 16 + (lane >> 2);
#pragma unroll
    for (int n = 0; n < 16; ++n) {
        const int d = n * 8 + (lane & 3) * 2;
#pragma unroll
        for (int rr = 0; rr < 2; ++rr) {
            const int qrow = qt * QROWS + r0 + rr * 8;
            const float inv = rr ? inv1 : inv0;
            const float2 gv = *(const float2*)(g_gate + (hb + qrow) * HD + d);
            const float sg0 = 1.0f / (1.0f + __expf(-gv.x));
            const float sg1 = 1.0f / (1.0f + __expf(-gv.y));
            const float x = sg0 * oacc[n][rr * 2 + 0] * inv;
            const float y = sg1 * oacc[n][rr * 2 + 1] * inv;
            uint32_t hi, lo;
            splith2(x, y, hi, lo);
            const size_t o = (size_t)(b * SEQ + qrow) * DMODEL + h * HD + d;
            *(uint32_t*)(g_th + o) = hi;
            *(uint32_t*)(g_tl + o) = lo;
        }
    }
}

// ---------------------------------------------------------------------------
extern "C" void kernel_launch(void* const* d_in, const int* in_sizes, int n_in,
                              void* d_out, int out_size)
{
    const float* hidden = (const float*)d_in[0];
    const float* W_in   = (const float*)d_in[1];
    const float* W_out  = (const float*)d_in[2];
    float* out = (float*)d_out;

    __half *ah, *win, *woh, *wol, *th, *tl;
    cudaGetSymbolAddress((void**)&ah,  g_ah);
    cudaGetSymbolAddress((void**)&win, g_win);
    cudaGetSymbolAddress((void**)&woh, g_woh);
    cudaGetSymbolAddress((void**)&wol, g_wol);
    cudaGetSymbolAddress((void**)&th,  g_th);
    cudaGetSymbolAddress((void**)&tl,  g_tl);

    cudaFuncSetAttribute(gemm_hmma<1>,
                         cudaFuncAttributeMaxDynamicSharedMemorySize, GSMEM);
    cudaFuncSetAttribute(gemm_hmma<3>,
                         cudaFuncAttributeMaxDynamicSharedMemorySize, GSMEM);
    cudaFuncSetAttribute(attn_hmma,
                         cudaFuncAttributeMaxDynamicSharedMemorySize, ATTN_SMEM);

    // prep: hidden -> single fp16; W_in -> single fp16 T; W_out -> split fp16 T
    round_plain<<<1024, 256>>>(hidden, ah, (size_t)ROWS * DMODEL / 4);
    transpose_round<<<dim3(NPROJ / 32, DMODEL / 32), dim3(32, 8)>>>(W_in, win,
                                                                    DMODEL, NPROJ);
    transpose_split<<<dim3(DMODEL / 32, DMODEL / 32), dim3(32, 8)>>>(W_out, woh, wol,
                                                                     DMODEL, DMODEL);

    // 1) proj GEMM (1-term fp16) -> q split + rmsnorm/scale, k/v single, gate fp32
    gemm_hmma<1><<<dim3(NPROJ / BN, ROWS / BM), 256, GSMEM>>>(
        ah, nullptr, win, nullptr, nullptr, ROWS, NPROJ, DMODEL, 1);

    // 2) fp16x2 flash attention + sigmoid gate -> g_th/g_tl
    attn_hmma<<<dim3(SEQ / QROWS, HEADS, NB), 512, ATTN_SMEM>>>();

    // 3) out = att @ W_out (3-term fp16: A split + B split)
    gemm_hmma<3><<<dim3(DMODEL / BN, ROWS / BM), 256, GSMEM>>>(
        th, tl, woh, wol, out, ROWS, DMODEL, DMODEL, 0);
}

// round 10
// speedup vs baseline: 1.9476x; 1.1206x over previous
#include <cuda_runtime.h>
#include <cuda_fp16.h>
#include <math.h>
#include <stdint.h>

// Problem constants
#define ROWS   4096          // B*S
#define DMODEL 2048
#define NPROJ  8192          // 4*DMODEL
#define HEADS  16
#define HD     128
#define SEQ    2048
#define NB     2
#define FP16MAX 65504.0f
#define RMS_EPS 1e-5f
#define ATTN_SCALE 0.08838834764831845f

// ---------------- scratch (allocation-free) ----------------
#define HSD ((size_t)NB * HEADS * SEQ * HD)
__device__ __half g_qh[HSD];                 // q single fp16 (rmsnorm+scale folded)
__device__ __half g_kh[HSD];                 // k single fp16
__device__ __half g_vh[HSD];                 // v single fp16
__device__ float  g_gate[HSD];
__device__ __half g_ah  [(size_t)ROWS * DMODEL];   // hidden rounded fp16
__device__ __half g_win [(size_t)NPROJ * DMODEL];  // W_in^T single fp16 [N,K]
__device__ __half g_woh [(size_t)DMODEL * DMODEL]; // W_out^T hi [N,K]
__device__ __half g_wol [(size_t)DMODEL * DMODEL]; // W_out^T lo
__device__ __half g_th  [(size_t)ROWS * DMODEL];   // attn out hi
__device__ __half g_tl  [(size_t)ROWS * DMODEL];   // attn out lo

// ---------------- PTX helpers (sm_80-portable only) ----------------
__device__ __forceinline__ uint32_t smem_u32(const void* p) {
    uint32_t a;
    asm("{ .reg .u64 t; cvta.to.shared.u64 t, %1; cvt.u32.u64 %0, t; }" : "=r"(a) : "l"(p));
    return a;
}
__device__ __forceinline__ void cp16(uint32_t saddr, const void* g) {
    asm volatile("cp.async.cg.shared.global [%0], [%1], 16;" :: "r"(saddr), "l"(g));
}
__device__ __forceinline__ void cp_commit() {
    asm volatile("cp.async.commit_group;" ::: "memory");
}
template <int N>
__device__ __forceinline__ void cp_wait() {
    asm volatile("cp.async.wait_group %0;" :: "n"(N) : "memory");
}
__device__ __forceinline__ void ldsm4(uint32_t* r, uint32_t a) {
    asm volatile("ldmatrix.sync.aligned.m8n8.x4.shared.b16 {%0,%1,%2,%3}, [%4];"
                 : "=r"(r[0]), "=r"(r[1]), "=r"(r[2]), "=r"(r[3]) : "r"(a));
}
__device__ __forceinline__ void ldsm4t(uint32_t* r, uint32_t a) {
    asm volatile("ldmatrix.sync.aligned.m8n8.x4.trans.shared.b16 {%0,%1,%2,%3}, [%4];"
                 : "=r"(r[0]), "=r"(r[1]), "=r"(r[2]), "=r"(r[3]) : "r"(a));
}
__device__ __forceinline__ void mma16816(float* c, const uint32_t* a, const uint32_t* b) {
    asm volatile(
        "mma.sync.aligned.m16n8k16.row.col.f32.f16.f16.f32 "
        "{%0,%1,%2,%3}, {%4,%5,%6,%7}, {%8,%9}, {%0,%1,%2,%3};"
        : "+f"(c[0]), "+f"(c[1]), "+f"(c[2]), "+f"(c[3])
        : "r"(a[0]), "r"(a[1]), "r"(a[2]), "r"(a[3]), "r"(b[0]), "r"(b[1]));
}
__device__ __forceinline__ void splith2(float x, float y, uint32_t& hi, uint32_t& lo) {
    __half2 h2 = __floats2half2_rn(x, y);
    float hx = __low2float(h2), hy = __high2float(h2);
    __half2 l2 = __floats2half2_rn(x - hx, y - hy);
    hi = *(uint32_t*)&h2;
    lo = *(uint32_t*)&l2;
}
__device__ __forceinline__ uint32_t roundh2(float x, float y) {
    __half2 h2 = __floats2half2_rn(x, y);
    return *(uint32_t*)&h2;
}

// ---------------- prep kernels ----------------
__global__ void round_plain(const float* __restrict__ in,
                            __half* __restrict__ hi, size_t n4)
{
    size_t i = (size_t)blockIdx.x * blockDim.x + threadIdx.x;
    size_t stride = (size_t)gridDim.x * blockDim.x;
    for (; i < n4; i += stride) {
        float4 x = ((const float4*)in)[i];
        ((uint32_t*)hi)[i * 2 + 0] = roundh2(x.x, x.y);
        ((uint32_t*)hi)[i * 2 + 1] = roundh2(x.z, x.w);
    }
}

__global__ void transpose_round(const float* __restrict__ in,
                                __half* __restrict__ hi, int R, int C)
{
    __shared__ float t[32][33];
    const int bx = blockIdx.x * 32, by = blockIdx.y * 32;
    const int tx = threadIdx.x, ty = threadIdx.y;
#pragma unroll
    for (int j = 0; j < 4; ++j)
        t[ty + 8 * j][tx] = in[(size_t)(by + ty + 8 * j) * C + bx + tx];
    __syncthreads();
#pragma unroll
    for (int j = 0; j < 4; ++j) {
        float v = t[tx][ty + 8 * j];
        hi[(size_t)(bx + ty + 8 * j) * R + by + tx] = __float2half_rn(v);
    }
}

__global__ void transpose_split(const float* __restrict__ in,
                                __half* __restrict__ hi,
                                __half* __restrict__ lo, int R, int C)
{
    __shared__ float t[32][33];
    const int bx = blockIdx.x * 32, by = blockIdx.y * 32;
    const int tx = threadIdx.x, ty = threadIdx.y;
#pragma unroll
    for (int j = 0; j < 4; ++j)
        t[ty + 8 * j][tx] = in[(size_t)(by + ty + 8 * j) * C + bx + tx];
    __syncthreads();
#pragma unroll
    for (int j = 0; j < 4; ++j) {
        float v = t[tx][ty + 8 * j];
        __half h = __float2half_rn(v);
        __half l = __float2half_rn(v - __half2float(h));
        size_t o = (size_t)(bx + ty + 8 * j) * R + by + tx;
        hi[o] = h;
        lo[o] = l;
    }
}

// ---------------- HMMA fp16 GEMM: C[M,N] = A[M,K] @ B[N,K]^T ----------------
// TERMS=1: round(A)*round(B).  TERMS=3: (Ahi+Alo)*Bhi + Ahi*Blo.
#define BM 128
#define BN 128
#define BK 32
#define ROWB 80
#define TILEB (128 * ROWB)          // 10240 per matrix
#define STAGEB (4 * TILEB)
#define GSMEM (2 * STAGEB)          // 81920

template <int TERMS>
__global__ __launch_bounds__(256)
void gemm_hmma(const __half* __restrict__ Ahi, const __half* __restrict__ Alo,
               const __half* __restrict__ Bhi, const __half* __restrict__ Blo,
               float* __restrict__ C, int M, int N, int K, int mode)
{
    extern __shared__ char smraw[];
    const uint32_t sb = smem_u32(smraw);

    const int tid = threadIdx.x, wid = tid >> 5, lane = tid & 31;
    const int bm = blockIdx.y * BM, bn = blockIdx.x * BN;
    const int wm = wid >> 1, wn = wid & 1;

    const __half* Ahi_p = Ahi + (size_t)bm * K;
    const __half* Alo_p = (TERMS >= 2) ? (Alo + (size_t)bm * K) : nullptr;
    const __half* Bhi_p = Bhi + (size_t)bn * K;
    const __half* Blo_p = (TERMS >= 3) ? (Blo + (size_t)bn * K) : nullptr;

    const int nk = K / BK;

    auto load_mat = [&](uint32_t dst, const __half* src, size_t kofs) {
#pragma unroll
        for (int i = 0; i < 2; ++i) {
            const int v = tid + i * 256;
            const int row = v >> 2, c = v & 3;
            cp16(dst + row * ROWB + c * 16, src + (size_t)row * K + kofs + c * 8);
        }
    };
    auto stage_load = [&](int s, int kc) {
        const uint32_t base = sb + s * STAGEB;
        const size_t kofs = (size_t)kc * BK;
        load_mat(base,             Ahi_p, kofs);
        if (TERMS >= 2) load_mat(base + TILEB, Alo_p, kofs);
        load_mat(base + 2 * TILEB, Bhi_p, kofs);
        if (TERMS >= 3) load_mat(base + 3 * TILEB, Blo_p, kofs);
    };

    float acc[16][4];
#pragma unroll
    for (int i = 0; i < 16; ++i)
#pragma unroll
        for (int j = 0; j < 4; ++j) acc[i][j] = 0.f;

    stage_load(0, 0); cp_commit();
    stage_load(1, 1); cp_commit();
    cp_wait<1>();
    __syncthreads();

    for (int c = 0; c < nk; ++c) {
        const int s = c & 1;
        const uint32_t Ah = sb + s * STAGEB;
        const uint32_t Al = Ah + TILEB;
        const uint32_t Bh = Ah + 2 * TILEB;
        const uint32_t Bl = Ah + 3 * TILEB;

#pragma unroll
        for (int ks = 0; ks < 2; ++ks) {
            uint32_t ah[2][4], al[2][4];
#pragma unroll
            for (int mt = 0; mt < 2; ++mt) {
                const uint32_t ro = (uint32_t)(wm * 32 + mt * 16 + (lane & 15)) * ROWB
                                  + ks * 32 + (lane >> 4) * 16;
                ldsm4(ah[mt], Ah + ro);
                if (TERMS >= 2) ldsm4(al[mt], Al + ro);
            }
#pragma unroll
            for (int bt = 0; bt < 4; ++bt) {
                const uint32_t ro = (uint32_t)(wn * 64 + bt * 16 + (lane & 15)) * ROWB
                                  + ks * 32 + (lane >> 4) * 16;
                uint32_t bh[4];
                ldsm4(bh, Bh + ro);
                const uint32_t b0h[2] = { bh[0], bh[2] }, b1h[2] = { bh[1], bh[3] };
#pragma unroll
                for (int mt = 0; mt < 2; ++mt) {
                    mma16816(acc[mt * 8 + bt * 2 + 0], ah[mt], b0h);
                    mma16816(acc[mt * 8 + bt * 2 + 1], ah[mt], b1h);
                    if (TERMS >= 2) {
                        mma16816(acc[mt * 8 + bt * 2 + 0], al[mt], b0h);
                        mma16816(acc[mt * 8 + bt * 2 + 1], al[mt], b1h);
                    }
                }
                if (TERMS >= 3) {
                    uint32_t bl[4];
                    ldsm4(bl, Bl + ro);
                    const uint32_t b0l[2] = { bl[0], bl[2] }, b1l[2] = { bl[1], bl[3] };
#pragma unroll
                    for (int mt = 0; mt < 2; ++mt) {
                        mma16816(acc[mt * 8 + bt * 2 + 0], ah[mt], b0l);
                        mma16816(acc[mt * 8 + bt * 2 + 1], ah[mt], b1l);
                    }
                }
            }
        }

        __syncthreads();
        if (c + 2 < nk) {
            stage_load(s, c + 2);
            cp_commit();
            cp_wait<1>();
        } else {
            cp_wait<0>();
        }
        __syncthreads();
    }

    const int group = bn >> 11;       // 0=q 1=k 2=v 3=g (mode 1 only)

    // ---- fused clamp+RMSNorm for q,k (mode 1) ----
    float* ssm = (float*)smraw;
    if (mode && group < 2) {
        float ssp[2][2] = { {0.f, 0.f}, {0.f, 0.f} };
#pragma unroll
        for (int mt = 0; mt < 2; ++mt)
#pragma unroll
            for (int bt = 0; bt < 4; ++bt)
#pragma unroll
                for (int half = 0; half < 2; ++half) {
                    float* a = acc[mt * 8 + bt * 2 + half];
#pragma unroll
                    for (int q = 0; q < 4; ++q) {
                        float v = fminf(fmaxf(a[q], -FP16MAX), FP16MAX);
                        a[q] = v;
                        ssp[mt][q >> 1] += v * v;
                    }
                }
#pragma unroll
        for (int mt = 0; mt < 2; ++mt)
#pragma unroll
            for (int hh = 0; hh < 2; ++hh) {
                float s0 = ssp[mt][hh];
                s0 += __shfl_xor_sync(0xffffffffu, s0, 1);
                s0 += __shfl_xor_sync(0xffffffffu, s0, 2);
                if ((lane & 3) == 0) {
                    const int row = wm * 32 + mt * 16 + (lane >> 2) + hh * 8;
                    ssm[wn * 128 + row] = s0;
                }
            }
        __syncthreads();
        const float post = (group == 0) ? ATTN_SCALE : 1.0f;
#pragma unroll
        for (int mt = 0; mt < 2; ++mt)
#pragma unroll
            for (int hh = 0; hh < 2; ++hh) {
                const int row = wm * 32 + mt * 16 + (lane >> 2) + hh * 8;
                const float tot = ssm[row] + ssm[128 + row];
                const float sc = rsqrtf(tot * (1.0f / 128.0f) + RMS_EPS) * post;
#pragma unroll
                for (int bt = 0; bt < 4; ++bt)
#pragma unroll
                    for (int half = 0; half < 2; ++half) {
                        acc[mt * 8 + bt * 2 + half][hh * 2 + 0] *= sc;
                        acc[mt * 8 + bt * 2 + half][hh * 2 + 1] *= sc;
                    }
            }
    }

    if (mode) {
        // q,k,v single fp16; gate fp32. Layout [b][h][s][d].
        const int hh = (bn >> 7) & 15;
        __half* dsth = (group == 0) ? g_qh : (group == 1) ? g_kh : g_vh;
#pragma unroll
        for (int mt = 0; mt < 2; ++mt)
#pragma unroll
            for (int bt = 0; bt < 4; ++bt)
#pragma unroll
                for (int half = 0; half < 2; ++half) {
                    const int d = wn * 64 + bt * 16 + half * 8 + (lane & 3) * 2;
                    float* a = acc[mt * 8 + bt * 2 + half];
#pragma unroll
                    for (int rr = 0; rr < 2; ++rr) {
                        const int row = bm + wm * 32 + mt * 16 + (lane >> 2) + rr * 8;
                        const int bb = row >> 11, s = row & 2047;
                        const size_t idx = ((size_t)(bb * HEADS + hh) * SEQ + s) * HD + d;
                        const float x = a[rr * 2 + 0], y = a[rr * 2 + 1];
                        if (group == 3) {
                            *(float2*)(g_gate + idx) = make_float2(x, y);
                        } else {
                            *(uint32_t*)(dsth + idx) = roundh2(x, y);
                        }
                    }
                }
    } else {
#pragma unroll
        for (int mt = 0; mt < 2; ++mt)
#pragma unroll
            for (int bt = 0; bt < 4; ++bt)
#pragma unroll
                for (int half = 0; half < 2; ++half) {
                    const int col = bn + wn * 64 + bt * 16 + half * 8 + (lane & 3) * 2;
                    const int r0 = bm + wm * 32 + mt * 16 + (lane >> 2);
                    float* a = acc[mt * 8 + bt * 2 + half];
                    *(float2*)(C + (size_t)r0 * N + col)       = make_float2(a[0], a[1]);
                    *(float2*)(C + (size_t)(r0 + 8) * N + col) = make_float2(a[2], a[3]);
                }
    }
}

// ---------------- HMMA fp16 1-term flash attention ----------------
// 512 threads = 16 warps, each warp 16 q rows -> 256 q rows per CTA.
// q,K,V single fp16. KV chunks of 32, double buffered.
#define AROWB 272                        // 128 fp16 = 256 B + 16 pad
#define QROWS 256
#define QT (QROWS * AROWB)               // 69632
#define KVR 32
#define KVB (KVR * AROWB)                // 8704
#define STG (2 * KVB)                    // k + v = 17408
#define ATTN_SMEM (QT + 2 * STG)         // 104448

__global__ __launch_bounds__(512, 1)
void attn_hmma()
{
    extern __shared__ char smraw[];
    const uint32_t sb = smem_u32(smraw);

    const int tid = threadIdx.x, w = tid >> 5, lane = tid & 31;
    const int qt = blockIdx.x, h = blockIdx.y, b = blockIdx.z;
    const size_t hb = ((size_t)b * HEADS + h) * SEQ;

    const __half* Qh_g = g_qh + (hb + qt * QROWS) * HD;
    const __half* Kh_g = g_kh + hb * HD;
    const __half* Vh_g = g_vh + hb * HD;

    auto loadKV = [&](int s, int kt) {
        const uint32_t base = sb + QT + s * STG;
        const size_t kv0 = (size_t)kt * KVR;
        const int row = tid >> 4, c = tid & 15;
        const uint32_t so = base + row * AROWB + c * 16;
        const size_t go = (kv0 + row) * HD + c * 8;
        cp16(so,       Kh_g + go);
        cp16(so + KVB, Vh_g + go);
    };

#pragma unroll
    for (int i = 0; i < 8; ++i) {
        const int v = tid + i * 512;
        const int row = v >> 4, c = v & 15;
        cp16(sb + row * AROWB + c * 16, Qh_g + (size_t)row * HD + c * 8);
    }
    loadKV(0, 0); cp_commit();
    loadKV(1, 1); cp_commit();
    cp_wait<1>();
    __syncthreads();

    float oacc[16][4];
#pragma unroll
    for (int i = 0; i < 16; ++i)
#pragma unroll
        for (int j = 0; j < 4; ++j) oacc[i][j] = 0.f;
    float m0 = -INFINITY, m1 = -INFINITY, l0 = 0.f, l1 = 0.f;

    const int nkt = SEQ / KVR;   // 64
    for (int c = 0; c < nkt; ++c) {
        const int s = c & 1;
        const uint32_t kbase = sb + QT + s * STG;

        // ---- S = q @ K^T (1-term) ----
        float sacc[4][4];
#pragma unroll
        for (int i = 0; i < 4; ++i)
#pragma unroll
            for (int j = 0; j < 4; ++j) sacc[i][j] = 0.f;

#pragma unroll
        for (int kt = 0; kt < 8; ++kt) {
            uint32_t ah[4];
            const uint32_t qo = (uint32_t)(w * 16 + (lane & 15)) * AROWB
                              + kt * 32 + (lane >> 4) * 16;
            ldsm4(ah, sb + qo);
#pragma unroll
            for (int g = 0; g < 2; ++g) {
                const uint32_t ko = kbase + (uint32_t)(g * 16 + (lane & 15)) * AROWB
                                  + kt * 32 + (lane >> 4) * 16;
                uint32_t bh[4];
                ldsm4(bh, ko);
                const uint32_t b0[2] = { bh[0], bh[2] }, b1[2] = { bh[1], bh[3] };
                mma16816(sacc[2 * g + 0], ah, b0);
                mma16816(sacc[2 * g + 1], ah, b1);
            }
        }

        // ---- online softmax ----
        float mx0 = -INFINITY, mx1 = -INFINITY;
#pragma unroll
        for (int j = 0; j < 4; ++j) {
            mx0 = fmaxf(mx0, fmaxf(sacc[j][0], sacc[j][1]));
            mx1 = fmaxf(mx1, fmaxf(sacc[j][2], sacc[j][3]));
        }
        mx0 = fmaxf(mx0, __shfl_xor_sync(0xffffffffu, mx0, 1));
        mx0 = fmaxf(mx0, __shfl_xor_sync(0xffffffffu, mx0, 2));
        mx1 = fmaxf(mx1, __shfl_xor_sync(0xffffffffu, mx1, 1));
        mx1 = fmaxf(mx1, __shfl_xor_sync(0xffffffffu, mx1, 2));
        const float mn0 = fmaxf(m0, mx0), mn1 = fmaxf(m1, mx1);
        const float corr0 = __expf(m0 - mn0), corr1 = __expf(m1 - mn1);
        m0 = mn0; m1 = mn1;
        float rs0 = 0.f, rs1 = 0.f;
#pragma unroll
        for (int j = 0; j < 4; ++j) {
            sacc[j][0] = __expf(sacc[j][0] - mn0);
            sacc[j][1] = __expf(sacc[j][1] - mn0);
            sacc[j][2] = __expf(sacc[j][2] - mn1);
            sacc[j][3] = __expf(sacc[j][3] - mn1);
            rs0 += sacc[j][0] + sacc[j][1];
            rs1 += sacc[j][2] + sacc[j][3];
        }
        rs0 += __shfl_xor_sync(0xffffffffu, rs0, 1);
        rs0 += __shfl_xor_sync(0xffffffffu, rs0, 2);
        rs1 += __shfl_xor_sync(0xffffffffu, rs1, 1);
        rs1 += __shfl_xor_sync(0xffffffffu, rs1, 2);
        l0 = l0 * corr0 + rs0;
        l1 = l1 * corr1 + rs1;
#pragma unroll
        for (int n = 0; n < 16; ++n) {
            oacc[n][0] *= corr0; oacc[n][1] *= corr0;
            oacc[n][2] *= corr1; oacc[n][3] *= corr1;
        }

        // ---- P (C-frag) -> A-frag single fp16 ----
        uint32_t pa[2][4];
#pragma unroll
        for (int kc = 0; kc < 2; ++kc) {
            pa[kc][0] = roundh2(sacc[2 * kc][0],     sacc[2 * kc][1]);
            pa[kc][1] = roundh2(sacc[2 * kc][2],     sacc[2 * kc][3]);
            pa[kc][2] = roundh2(sacc[2 * kc + 1][0], sacc[2 * kc + 1][1]);
            pa[kc][3] = roundh2(sacc[2 * kc + 1][2], sacc[2 * kc + 1][3]);
        }

        // ---- O += P @ V (1-term, V via ldmatrix.trans) ----
#pragma unroll
        for (int kc = 0; kc < 2; ++kc) {
#pragma unroll
            for (int g2 = 0; g2 < 8; ++g2) {
                const uint32_t vo = kbase + KVB
                                  + (uint32_t)(kc * 16 + (lane & 15)) * AROWB
                                  + (g2 * 16 + (lane >> 4) * 8) * 2;
                uint32_t vh[4];
                ldsm4t(vh, vo);
                const uint32_t b0[2] = { vh[0], vh[1] }, b1[2] = { vh[2], vh[3] };
                mma16816(oacc[2 * g2 + 0], pa[kc], b0);
                mma16816(oacc[2 * g2 + 1], pa[kc], b1);
            }
        }

        __syncthreads();
        if (c + 2 < nkt) {
            loadKV(s, c + 2);
            cp_commit();
            cp_wait<1>();
        } else {
            cp_wait<0>();
        }
        __syncthreads();
    }

    // ---- epilogue: O/l, sigmoid gate, split hi/lo fp16 for GEMM2 ----
    const float inv0 = 1.0f / l0, inv1 = 1.0f / l1;
    const int r0 = w * 16 + (lane >> 2);
#pragma unroll
    for (int n = 0; n < 16; ++n) {
        const int d = n * 8 + (lane & 3) * 2;
#pragma unroll
        for (int rr = 0; rr < 2; ++rr) {
            const int qrow = qt * QROWS + r0 + rr * 8;
            const float inv = rr ? inv1 : inv0;
            const float2 gv = *(const float2*)(g_gate + (hb + qrow) * HD + d);
            const float sg0 = 1.0f / (1.0f + __expf(-gv.x));
            const float sg1 = 1.0f / (1.0f + __expf(-gv.y));
            const float x = sg0 * oacc[n][rr * 2 + 0] * inv;
            const float y = sg1 * oacc[n][rr * 2 + 1] * inv;
            uint32_t hi, lo;
            splith2(x, y, hi, lo);
            const size_t o = (size_t)(b * SEQ + qrow) * DMODEL + h * HD + d;
            *(uint32_t*)(g_th + o) = hi;
            *(uint32_t*)(g_tl + o) = lo;
        }
    }
}

// ---------------------------------------------------------------------------
extern "C" void kernel_launch(void* const* d_in, const int* in_sizes, int n_in,
                              void* d_out, int out_size)
{
    const float* hidden = (const float*)d_in[0];
    const float* W_in   = (const float*)d_in[1];
    const float* W_out  = (const float*)d_in[2];
    float* out = (float*)d_out;

    __half *ah, *win, *woh, *wol, *th, *tl;
    cudaGetSymbolAddress((void**)&ah,  g_ah);
    cudaGetSymbolAddress((void**)&win, g_win);
    cudaGetSymbolAddress((void**)&woh, g_woh);
    cudaGetSymbolAddress((void**)&wol, g_wol);
    cudaGetSymbolAddress((void**)&th,  g_th);
    cudaGetSymbolAddress((void**)&tl,  g_tl);

    cudaFuncSetAttribute(gemm_hmma<1>,
                         cudaFuncAttributeMaxDynamicSharedMemorySize, GSMEM);
    cudaFuncSetAttribute(gemm_hmma<3>,
                         cudaFuncAttributeMaxDynamicSharedMemorySize, GSMEM);
    cudaFuncSetAttribute(attn_hmma,
                         cudaFuncAttributeMaxDynamicSharedMemorySize, ATTN_SMEM);

    // prep: hidden -> single fp16; W_in -> single fp16 T; W_out -> split fp16 T
    round_plain<<<1024, 256>>>(hidden, ah, (size_t)ROWS * DMODEL / 4);
    transpose_round<<<dim3(NPROJ / 32, DMODEL / 32), dim3(32, 8)>>>(W_in, win,
                                                                    DMODEL, NPROJ);
    transpose_split<<<dim3(DMODEL / 32, DMODEL / 32), dim3(32, 8)>>>(W_out, woh, wol,
                                                                     DMODEL, DMODEL);

    // 1) proj GEMM (1-term fp16) -> q/k/v single fp16 (+rmsnorm), gate fp32
    gemm_hmma<1><<<dim3(NPROJ / BN, ROWS / BM), 256, GSMEM>>>(
        ah, nullptr, win, nullptr, nullptr, ROWS, NPROJ, DMODEL, 1);

    // 2) fp16 1-term flash attention + sigmoid gate -> g_th/g_tl
    attn_hmma<<<dim3(SEQ / QROWS, HEADS, NB), 512, ATTN_SMEM>>>();

    // 3) out = att @ W_out (3-term fp16: A split + B split, accuracy anchor)
    gemm_hmma<3><<<dim3(DMODEL / BN, ROWS / BM), 256, GSMEM>>>(
        th, tl, woh, wol, out, ROWS, DMODEL, DMODEL, 0);
}

// round 11
// speedup vs baseline: 2.3726x; 1.2182x over previous
#include <cuda_runtime.h>
#include <cuda_fp16.h>
#include <math.h>
#include <stdint.h>

// Problem constants
#define ROWS   4096          // B*S
#define DMODEL 2048
#define NPROJ  8192          // 4*DMODEL
#define HEADS  16
#define HD     128
#define SEQ    2048
#define NB     2
#define FP16MAX 65504.0f
#define RMS_EPS 1e-5f
#define ATTN_SCALE 0.08838834764831845f

// ---------------- scratch (allocation-free) ----------------
#define HSD ((size_t)NB * HEADS * SEQ * HD)
__device__ __half g_qh[HSD];                 // q single fp16 (rmsnorm+scale folded)
__device__ __half g_kh[HSD];                 // k single fp16
__device__ __half g_vh[HSD];                 // v single fp16
__device__ float  g_gate[HSD];
__device__ __half g_ah  [(size_t)ROWS * DMODEL];   // hidden rounded fp16
__device__ __half g_win [(size_t)NPROJ * DMODEL];  // W_in^T single fp16 [N,K]
__device__ __half g_wo  [(size_t)DMODEL * DMODEL]; // W_out^T single fp16 [N,K]
__device__ __half g_th  [(size_t)ROWS * DMODEL];   // attn out rounded fp16

// ---------------- PTX helpers (sm_80-portable only) ----------------
__device__ __forceinline__ uint32_t smem_u32(const void* p) {
    uint32_t a;
    asm("{ .reg .u64 t; cvta.to.shared.u64 t, %1; cvt.u32.u64 %0, t; }" : "=r"(a) : "l"(p));
    return a;
}
__device__ __forceinline__ void cp16(uint32_t saddr, const void* g) {
    asm volatile("cp.async.cg.shared.global [%0], [%1], 16;" :: "r"(saddr), "l"(g));
}
__device__ __forceinline__ void cp_commit() {
    asm volatile("cp.async.commit_group;" ::: "memory");
}
template <int N>
__device__ __forceinline__ void cp_wait() {
    asm volatile("cp.async.wait_group %0;" :: "n"(N) : "memory");
}
__device__ __forceinline__ void ldsm4(uint32_t* r, uint32_t a) {
    asm volatile("ldmatrix.sync.aligned.m8n8.x4.shared.b16 {%0,%1,%2,%3}, [%4];"
                 : "=r"(r[0]), "=r"(r[1]), "=r"(r[2]), "=r"(r[3]) : "r"(a));
}
__device__ __forceinline__ void ldsm4t(uint32_t* r, uint32_t a) {
    asm volatile("ldmatrix.sync.aligned.m8n8.x4.trans.shared.b16 {%0,%1,%2,%3}, [%4];"
                 : "=r"(r[0]), "=r"(r[1]), "=r"(r[2]), "=r"(r[3]) : "r"(a));
}
__device__ __forceinline__ void mma16816(float* c, const uint32_t* a, const uint32_t* b) {
    asm volatile(
        "mma.sync.aligned.m16n8k16.row.col.f32.f16.f16.f32 "
        "{%0,%1,%2,%3}, {%4,%5,%6,%7}, {%8,%9}, {%0,%1,%2,%3};"
        : "+f"(c[0]), "+f"(c[1]), "+f"(c[2]), "+f"(c[3])
        : "r"(a[0]), "r"(a[1]), "r"(a[2]), "r"(a[3]), "r"(b[0]), "r"(b[1]));
}
__device__ __forceinline__ uint32_t roundh2(float x, float y) {
    __half2 h2 = __floats2half2_rn(x, y);
    return *(uint32_t*)&h2;
}

// ---------------- prep kernels ----------------
__global__ void round_plain(const float* __restrict__ in,
                            __half* __restrict__ hi, size_t n4)
{
    size_t i = (size_t)blockIdx.x * blockDim.x + threadIdx.x;
    size_t stride = (size_t)gridDim.x * blockDim.x;
    for (; i < n4; i += stride) {
        float4 x = ((const float4*)in)[i];
        ((uint32_t*)hi)[i * 2 + 0] = roundh2(x.x, x.y);
        ((uint32_t*)hi)[i * 2 + 1] = roundh2(x.z, x.w);
    }
}

__global__ void transpose_round(const float* __restrict__ in,
                                __half* __restrict__ hi, int R, int C)
{
    __shared__ float t[32][33];
    const int bx = blockIdx.x * 32, by = blockIdx.y * 32;
    const int tx = threadIdx.x, ty = threadIdx.y;
#pragma unroll
    for (int j = 0; j < 4; ++j)
        t[ty + 8 * j][tx] = in[(size_t)(by + ty + 8 * j) * C + bx + tx];
    __syncthreads();
#pragma unroll
    for (int j = 0; j < 4; ++j) {
        float v = t[tx][ty + 8 * j];
        hi[(size_t)(bx + ty + 8 * j) * R + by + tx] = __float2half_rn(v);
    }
}

// ---------------- HMMA fp16 1-term GEMM: C[M,N] = A[M,K] @ B[N,K]^T ----------------
#define BM 128
#define BN 128
#define BK 32
#define ROWB 80
#define TILEB (128 * ROWB)          // 10240 per matrix
#define STAGEB (2 * TILEB)          // A + B
#define GSMEM (2 * STAGEB)          // 40960

__global__ __launch_bounds__(256)
void gemm_hmma(const __half* __restrict__ A, const __half* __restrict__ B,
               float* __restrict__ C, int M, int N, int K, int mode)
{
    extern __shared__ char smraw[];
    const uint32_t sb = smem_u32(smraw);

    const int tid = threadIdx.x, wid = tid >> 5, lane = tid & 31;
    const int bm = blockIdx.y * BM, bn = blockIdx.x * BN;
    const int wm = wid >> 1, wn = wid & 1;

    const __half* A_p = A + (size_t)bm * K;
    const __half* B_p = B + (size_t)bn * K;

    const int nk = K / BK;

    auto load_mat = [&](uint32_t dst, const __half* src, size_t kofs) {
#pragma unroll
        for (int i = 0; i < 2; ++i) {
            const int v = tid + i * 256;
            const int row = v >> 2, c = v & 3;
            cp16(dst + row * ROWB + c * 16, src + (size_t)row * K + kofs + c * 8);
        }
    };
    auto stage_load = [&](int s, int kc) {
        const uint32_t base = sb + s * STAGEB;
        const size_t kofs = (size_t)kc * BK;
        load_mat(base,         A_p, kofs);
        load_mat(base + TILEB, B_p, kofs);
    };

    float acc[16][4];
#pragma unroll
    for (int i = 0; i < 16; ++i)
#pragma unroll
        for (int j = 0; j < 4; ++j) acc[i][j] = 0.f;

    stage_load(0, 0); cp_commit();
    stage_load(1, 1); cp_commit();
    cp_wait<1>();
    __syncthreads();

    for (int c = 0; c < nk; ++c) {
        const int s = c & 1;
        const uint32_t Ah = sb + s * STAGEB;
        const uint32_t Bh = Ah + TILEB;

#pragma unroll
        for (int ks = 0; ks < 2; ++ks) {
            uint32_t ah[2][4];
#pragma unroll
            for (int mt = 0; mt < 2; ++mt) {
                const uint32_t ro = (uint32_t)(wm * 32 + mt * 16 + (lane & 15)) * ROWB
                                  + ks * 32 + (lane >> 4) * 16;
                ldsm4(ah[mt], Ah + ro);
            }
#pragma unroll
            for (int bt = 0; bt < 4; ++bt) {
                const uint32_t ro = (uint32_t)(wn * 64 + bt * 16 + (lane & 15)) * ROWB
                                  + ks * 32 + (lane >> 4) * 16;
                uint32_t bh[4];
                ldsm4(bh, Bh + ro);
                const uint32_t b0h[2] = { bh[0], bh[2] }, b1h[2] = { bh[1], bh[3] };
#pragma unroll
                for (int mt = 0; mt < 2; ++mt) {
                    mma16816(acc[mt * 8 + bt * 2 + 0], ah[mt], b0h);
                    mma16816(acc[mt * 8 + bt * 2 + 1], ah[mt], b1h);
                }
            }
        }

        __syncthreads();
        if (c + 2 < nk) {
            stage_load(s, c + 2);
            cp_commit();
            cp_wait<1>();
        } else {
            cp_wait<0>();
        }
        __syncthreads();
    }

    const int group = bn >> 11;       // 0=q 1=k 2=v 3=g (mode 1 only)

    // ---- fused clamp+RMSNorm for q,k (mode 1) ----
    float* ssm = (float*)smraw;
    if (mode && group < 2) {
        float ssp[2][2] = { {0.f, 0.f}, {0.f, 0.f} };
#pragma unroll
        for (int mt = 0; mt < 2; ++mt)
#pragma unroll
            for (int bt = 0; bt < 4; ++bt)
#pragma unroll
                for (int half = 0; half < 2; ++half) {
                    float* a = acc[mt * 8 + bt * 2 + half];
#pragma unroll
                    for (int q = 0; q < 4; ++q) {
                        float v = fminf(fmaxf(a[q], -FP16MAX), FP16MAX);
                        a[q] = v;
                        ssp[mt][q >> 1] += v * v;
                    }
                }
#pragma unroll
        for (int mt = 0; mt < 2; ++mt)
#pragma unroll
            for (int hh = 0; hh < 2; ++hh) {
                float s0 = ssp[mt][hh];
                s0 += __shfl_xor_sync(0xffffffffu, s0, 1);
                s0 += __shfl_xor_sync(0xffffffffu, s0, 2);
                if ((lane & 3) == 0) {
                    const int row = wm * 32 + mt * 16 + (lane >> 2) + hh * 8;
                    ssm[wn * 128 + row] = s0;
                }
            }
        __syncthreads();
        const float post = (group == 0) ? ATTN_SCALE : 1.0f;
#pragma unroll
        for (int mt = 0; mt < 2; ++mt)
#pragma unroll
            for (int hh = 0; hh < 2; ++hh) {
                const int row = wm * 32 + mt * 16 + (lane >> 2) + hh * 8;
                const float tot = ssm[row] + ssm[128 + row];
                const float sc = rsqrtf(tot * (1.0f / 128.0f) + RMS_EPS) * post;
#pragma unroll
                for (int bt = 0; bt < 4; ++bt)
#pragma unroll
                    for (int half = 0; half < 2; ++half) {
                        acc[mt * 8 + bt * 2 + half][hh * 2 + 0] *= sc;
                        acc[mt * 8 + bt * 2 + half][hh * 2 + 1] *= sc;
                    }
            }
    }

    if (mode) {
        // q,k,v single fp16; gate fp32. Layout [b][h][s][d].
        const int hh = (bn >> 7) & 15;
        __half* dsth = (group == 0) ? g_qh : (group == 1) ? g_kh : g_vh;
#pragma unroll
        for (int mt = 0; mt < 2; ++mt)
#pragma unroll
            for (int bt = 0; bt < 4; ++bt)
#pragma unroll
                for (int half = 0; half < 2; ++half) {
                    const int d = wn * 64 + bt * 16 + half * 8 + (lane & 3) * 2;
                    float* a = acc[mt * 8 + bt * 2 + half];
#pragma unroll
                    for (int rr = 0; rr < 2; ++rr) {
                        const int row = bm + wm * 32 + mt * 16 + (lane >> 2) + rr * 8;
                        const int bb = row >> 11, s = row & 2047;
                        const size_t idx = ((size_t)(bb * HEADS + hh) * SEQ + s) * HD + d;
                        const float x = a[rr * 2 + 0], y = a[rr * 2 + 1];
                        if (group == 3) {
                            *(float2*)(g_gate + idx) = make_float2(x, y);
                        } else {
                            *(uint32_t*)(dsth + idx) = roundh2(x, y);
                        }
                    }
                }
    } else {
#pragma unroll
        for (int mt = 0; mt < 2; ++mt)
#pragma unroll
            for (int bt = 0; bt < 4; ++bt)
#pragma unroll
                for (int half = 0; half < 2; ++half) {
                    const int col = bn + wn * 64 + bt * 16 + half * 8 + (lane & 3) * 2;
                    const int r0 = bm + wm * 32 + mt * 16 + (lane >> 2);
                    float* a = acc[mt * 8 + bt * 2 + half];
                    *(float2*)(C + (size_t)r0 * N + col)       = make_float2(a[0], a[1]);
                    *(float2*)(C + (size_t)(r0 + 8) * N + col) = make_float2(a[2], a[3]);
                }
    }
}

// ---------------- HMMA fp16 1-term flash attention ----------------
// 512 threads = 16 warps, each warp 16 q rows -> 256 q rows per CTA.
// q,K,V single fp16. KV chunks of 32, double buffered.
#define AROWB 272                        // 128 fp16 = 256 B + 16 pad
#define QROWS 256
#define QT (QROWS * AROWB)               // 69632
#define KVR 32
#define KVB (KVR * AROWB)                // 8704
#define STG (2 * KVB)                    // k + v = 17408
#define ATTN_SMEM (QT + 2 * STG)         // 104448

__global__ __launch_bounds__(512, 1)
void attn_hmma()
{
    extern __shared__ char smraw[];
    const uint32_t sb = smem_u32(smraw);

    const int tid = threadIdx.x, w = tid >> 5, lane = tid & 31;
    const int qt = blockIdx.x, h = blockIdx.y, b = blockIdx.z;
    const size_t hb = ((size_t)b * HEADS + h) * SEQ;

    const __half* Qh_g = g_qh + (hb + qt * QROWS) * HD;
    const __half* Kh_g = g_kh + hb * HD;
    const __half* Vh_g = g_vh + hb * HD;

    auto loadKV = [&](int s, int kt) {
        const uint32_t base = sb + QT + s * STG;
        const size_t kv0 = (size_t)kt * KVR;
        const int row = tid >> 4, c = tid & 15;
        const uint32_t so = base + row * AROWB + c * 16;
        const size_t go = (kv0 + row) * HD + c * 8;
        cp16(so,       Kh_g + go);
        cp16(so + KVB, Vh_g + go);
    };

#pragma unroll
    for (int i = 0; i < 8; ++i) {
        const int v = tid + i * 512;
        const int row = v >> 4, c = v & 15;
        cp16(sb + row * AROWB + c * 16, Qh_g + (size_t)row * HD + c * 8);
    }
    loadKV(0, 0); cp_commit();
    loadKV(1, 1); cp_commit();
    cp_wait<1>();
    __syncthreads();

    float oacc[16][4];
#pragma unroll
    for (int i = 0; i < 16; ++i)
#pragma unroll
        for (int j = 0; j < 4; ++j) oacc[i][j] = 0.f;
    float m0 = -INFINITY, m1 = -INFINITY, l0 = 0.f, l1 = 0.f;

    const int nkt = SEQ / KVR;   // 64
    for (int c = 0; c < nkt; ++c) {
        const int s = c & 1;
        const uint32_t kbase = sb + QT + s * STG;

        // ---- S = q @ K^T (1-term) ----
        float sacc[4][4];
#pragma unroll
        for (int i = 0; i < 4; ++i)
#pragma unroll
            for (int j = 0; j < 4; ++j) sacc[i][j] = 0.f;

#pragma unroll
        for (int kt = 0; kt < 8; ++kt) {
            uint32_t ah[4];
            const uint32_t qo = (uint32_t)(w * 16 + (lane & 15)) * AROWB
                              + kt * 32 + (lane >> 4) * 16;
            ldsm4(ah, sb + qo);
#pragma unroll
            for (int g = 0; g < 2; ++g) {
                const uint32_t ko = kbase + (uint32_t)(g * 16 + (lane & 15)) * AROWB
                                  + kt * 32 + (lane >> 4) * 16;
                uint32_t bh[4];
                ldsm4(bh, ko);
                const uint32_t b0[2] = { bh[0], bh[2] }, b1[2] = { bh[1], bh[3] };
                mma16816(sacc[2 * g + 0], ah, b0);
                mma16816(sacc[2 * g + 1], ah, b1);
            }
        }

        // ---- online softmax ----
        float mx0 = -INFINITY, mx1 = -INFINITY;
#pragma unroll
        for (int j = 0; j < 4; ++j) {
            mx0 = fmaxf(mx0, fmaxf(sacc[j][0], sacc[j][1]));
            mx1 = fmaxf(mx1, fmaxf(sacc[j][2], sacc[j][3]));
        }
        mx0 = fmaxf(mx0, __shfl_xor_sync(0xffffffffu, mx0, 1));
        mx0 = fmaxf(mx0, __shfl_xor_sync(0xffffffffu, mx0, 2));
        mx1 = fmaxf(mx1, __shfl_xor_sync(0xffffffffu, mx1, 1));
        mx1 = fmaxf(mx1, __shfl_xor_sync(0xffffffffu, mx1, 2));
        const float mn0 = fmaxf(m0, mx0), mn1 = fmaxf(m1, mx1);
        const float corr0 = __expf(m0 - mn0), corr1 = __expf(m1 - mn1);
        m0 = mn0; m1 = mn1;
        float rs0 = 0.f, rs1 = 0.f;
#pragma unroll
        for (int j = 0; j < 4; ++j) {
            sacc[j][0] = __expf(sacc[j][0] - mn0);
            sacc[j][1] = __expf(sacc[j][1] - mn0);
            sacc[j][2] = __expf(sacc[j][2] - mn1);
            sacc[j][3] = __expf(sacc[j][3] - mn1);
            rs0 += sacc[j][0] + sacc[j][1];
            rs1 += sacc[j][2] + sacc[j][3];
        }
        rs0 += __shfl_xor_sync(0xffffffffu, rs0, 1);
        rs0 += __shfl_xor_sync(0xffffffffu, rs0, 2);
        rs1 += __shfl_xor_sync(0xffffffffu, rs1, 1);
        rs1 += __shfl_xor_sync(0xffffffffu, rs1, 2);
        l0 = l0 * corr0 + rs0;
        l1 = l1 * corr1 + rs1;
#pragma unroll
        for (int n = 0; n < 16; ++n) {
            oacc[n][0] *= corr0; oacc[n][1] *= corr0;
            oacc[n][2] *= corr1; oacc[n][3] *= corr1;
        }

        // ---- P (C-frag) -> A-frag single fp16 ----
        uint32_t pa[2][4];
#pragma unroll
        for (int kc = 0; kc < 2; ++kc) {
            pa[kc][0] = roundh2(sacc[2 * kc][0],     sacc[2 * kc][1]);
            pa[kc][1] = roundh2(sacc[2 * kc][2],     sacc[2 * kc][3]);
            pa[kc][2] = roundh2(sacc[2 * kc + 1][0], sacc[2 * kc + 1][1]);
            pa[kc][3] = roundh2(sacc[2 * kc + 1][2], sacc[2 * kc + 1][3]);
        }

        // ---- O += P @ V (1-term, V via ldmatrix.trans) ----
#pragma unroll
        for (int kc = 0; kc < 2; ++kc) {
#pragma unroll
            for (int g2 = 0; g2 < 8; ++g2) {
                const uint32_t vo = kbase + KVB
                                  + (uint32_t)(kc * 16 + (lane & 15)) * AROWB
                                  + (g2 * 16 + (lane >> 4) * 8) * 2;
                uint32_t vh[4];
                ldsm4t(vh, vo);
                const uint32_t b0[2] = { vh[0], vh[1] }, b1[2] = { vh[2], vh[3] };
                mma16816(oacc[2 * g2 + 0], pa[kc], b0);
                mma16816(oacc[2 * g2 + 1], pa[kc], b1);
            }
        }

        __syncthreads();
        if (c + 2 < nkt) {
            loadKV(s, c + 2);
            cp_commit();
            cp_wait<1>();
        } else {
            cp_wait<0>();
        }
        __syncthreads();
    }

    // ---- epilogue: O/l, sigmoid gate, rounded fp16 for GEMM2 ----
    const float inv0 = 1.0f / l0, inv1 = 1.0f / l1;
    const int r0 = w * 16 + (lane >> 2);
#pragma unroll
    for (int n = 0; n < 16; ++n) {
        const int d = n * 8 + (lane & 3) * 2;
#pragma unroll
        for (int rr = 0; rr < 2; ++rr) {
            const int qrow = qt * QROWS + r0 + rr * 8;
            const float inv = rr ? inv1 : inv0;
            const float2 gv = *(const float2*)(g_gate + (hb + qrow) * HD + d);
            const float sg0 = 1.0f / (1.0f + __expf(-gv.x));
            const float sg1 = 1.0f / (1.0f + __expf(-gv.y));
            const float x = sg0 * oacc[n][rr * 2 + 0] * inv;
            const float y = sg1 * oacc[n][rr * 2 + 1] * inv;
            const size_t o = (size_t)(b * SEQ + qrow) * DMODEL + h * HD + d;
            *(uint32_t*)(g_th + o) = roundh2(x, y);
        }
    }
}

// ---------------------------------------------------------------------------
extern "C" void kernel_launch(void* const* d_in, const int* in_sizes, int n_in,
                              void* d_out, int out_size)
{
    const float* hidden = (const float*)d_in[0];
    const float* W_in   = (const float*)d_in[1];
    const float* W_out  = (const float*)d_in[2];
    float* out = (float*)d_out;

    __half *ah, *win, *wo, *th;
    cudaGetSymbolAddress((void**)&ah,  g_ah);
    cudaGetSymbolAddress((void**)&win, g_win);
    cudaGetSymbolAddress((void**)&wo,  g_wo);
    cudaGetSymbolAddress((void**)&th,  g_th);

    cudaFuncSetAttribute(gemm_hmma,
                         cudaFuncAttributeMaxDynamicSharedMemorySize, GSMEM);
    cudaFuncSetAttribute(attn_hmma,
                         cudaFuncAttributeMaxDynamicSharedMemorySize, ATTN_SMEM);

    // prep: hidden -> fp16; W_in -> fp16 T; W_out -> fp16 T
    round_plain<<<1024, 256>>>(hidden, ah, (size_t)ROWS * DMODEL / 4);
    transpose_round<<<dim3(NPROJ / 32, DMODEL / 32), dim3(32, 8)>>>(W_in, win,
                                                                    DMODEL, NPROJ);
    transpose_round<<<dim3(DMODEL / 32, DMODEL / 32), dim3(32, 8)>>>(W_out, wo,
                                                                     DMODEL, DMODEL);

    // 1) proj GEMM (1-term fp16) -> q/k/v single fp16 (+rmsnorm), gate fp32
    gemm_hmma<<<dim3(NPROJ / BN, ROWS / BM), 256, GSMEM>>>(
        ah, win, nullptr, ROWS, NPROJ, DMODEL, 1);

    // 2) fp16 1-term flash attention + sigmoid gate -> g_th
    attn_hmma<<<dim3(SEQ / QROWS, HEADS, NB), 512, ATTN_SMEM>>>();

    // 3) out = att @ W_out (1-term fp16)
    gemm_hmma<<<dim3(DMODEL / BN, ROWS / BM), 256, GSMEM>>>(
        th, wo, out, ROWS, DMODEL, DMODEL, 0);
}

// round 12
// speedup vs baseline: 2.6988x; 1.1375x over previous
#include <cuda_runtime.h>
#include <cuda_fp16.h>
#include <math.h>
#include <stdint.h>

// Problem constants
#define ROWS   4096          // B*S
#define DMODEL 2048
#define NPROJ  8192          // 4*DMODEL
#define HEADS  16
#define HD     128
#define SEQ    2048
#define NB     2
#define FP16MAX 65504.0f
#define RMS_EPS 1e-5f
// 1/sqrt(128) * log2(e): q pre-scale so softmax can use exp2 directly
#define ATTN_SCALE_L2E (0.08838834764831845f * 1.4426950408889634f)

// ---------------- scratch (allocation-free) ----------------
#define HSD ((size_t)NB * HEADS * SEQ * HD)
__device__ __half g_qh[HSD];                 // q fp16 (rmsnorm*scale*log2e folded)
__device__ __half g_kh[HSD];                 // k fp16
__device__ __half g_vh[HSD];                 // v fp16
__device__ __half g_gate[HSD];               // gate fp16
__device__ __half g_ah  [(size_t)ROWS * DMODEL];   // hidden rounded fp16
__device__ __half g_win [(size_t)NPROJ * DMODEL];  // W_in^T fp16 [N,K]
__device__ __half g_wo  [(size_t)DMODEL * DMODEL]; // W_out^T fp16 [N,K]
__device__ __half g_th  [(size_t)ROWS * DMODEL];   // attn out rounded fp16

// ---------------- PTX helpers (sm_80-portable only) ----------------
__device__ __forceinline__ uint32_t smem_u32(const void* p) {
    uint32_t a;
    asm("{ .reg .u64 t; cvta.to.shared.u64 t, %1; cvt.u32.u64 %0, t; }" : "=r"(a) : "l"(p));
    return a;
}
__device__ __forceinline__ void cp16(uint32_t saddr, const void* g) {
    asm volatile("cp.async.cg.shared.global [%0], [%1], 16;" :: "r"(saddr), "l"(g));
}
__device__ __forceinline__ void cp_commit() {
    asm volatile("cp.async.commit_group;" ::: "memory");
}
template <int N>
__device__ __forceinline__ void cp_wait() {
    asm volatile("cp.async.wait_group %0;" :: "n"(N) : "memory");
}
__device__ __forceinline__ void ldsm4(uint32_t* r, uint32_t a) {
    asm volatile("ldmatrix.sync.aligned.m8n8.x4.shared.b16 {%0,%1,%2,%3}, [%4];"
                 : "=r"(r[0]), "=r"(r[1]), "=r"(r[2]), "=r"(r[3]) : "r"(a));
}
__device__ __forceinline__ void ldsm4t(uint32_t* r, uint32_t a) {
    asm volatile("ldmatrix.sync.aligned.m8n8.x4.trans.shared.b16 {%0,%1,%2,%3}, [%4];"
                 : "=r"(r[0]), "=r"(r[1]), "=r"(r[2]), "=r"(r[3]) : "r"(a));
}
__device__ __forceinline__ void mma16816(float* c, const uint32_t* a, const uint32_t* b) {
    asm volatile(
        "mma.sync.aligned.m16n8k16.row.col.f32.f16.f16.f32 "
        "{%0,%1,%2,%3}, {%4,%5,%6,%7}, {%8,%9}, {%0,%1,%2,%3};"
        : "+f"(c[0]), "+f"(c[1]), "+f"(c[2]), "+f"(c[3])
        : "r"(a[0]), "r"(a[1]), "r"(a[2]), "r"(a[3]), "r"(b[0]), "r"(b[1]));
}
__device__ __forceinline__ uint32_t roundh2(float x, float y) {
    __half2 h2 = __floats2half2_rn(x, y);
    return *(uint32_t*)&h2;
}
__device__ __forceinline__ float exp2fa(float x) {
    float r;
    asm("ex2.approx.f32 %0, %1;" : "=f"(r) : "f"(x));
    return r;
}

// ---------------- prep kernels ----------------
__global__ void round_plain(const float* __restrict__ in,
                            __half* __restrict__ hi, size_t n4)
{
    size_t i = (size_t)blockIdx.x * blockDim.x + threadIdx.x;
    size_t stride = (size_t)gridDim.x * blockDim.x;
    for (; i < n4; i += stride) {
        float4 x = ((const float4*)in)[i];
        ((uint32_t*)hi)[i * 2 + 0] = roundh2(x.x, x.y);
        ((uint32_t*)hi)[i * 2 + 1] = roundh2(x.z, x.w);
    }
}

__global__ void transpose_round(const float* __restrict__ in,
                                __half* __restrict__ hi, int R, int C)
{
    __shared__ float t[32][33];
    const int bx = blockIdx.x * 32, by = blockIdx.y * 32;
    const int tx = threadIdx.x, ty = threadIdx.y;
#pragma unroll
    for (int j = 0; j < 4; ++j)
        t[ty + 8 * j][tx] = in[(size_t)(by + ty + 8 * j) * C + bx + tx];
    __syncthreads();
#pragma unroll
    for (int j = 0; j < 4; ++j) {
        float v = t[tx][ty + 8 * j];
        hi[(size_t)(bx + ty + 8 * j) * R + by + tx] = __float2half_rn(v);
    }
}

// ---------------- HMMA fp16 1-term GEMM: C[M,N] = A[M,K] @ B[N,K]^T ----------------
// 128x128 block tile, BK=64, 8 warps (4m x 2n), 2-stage cp.async.
#define BM 128
#define BN 128
#define BK 64
#define ROWB 144                    // 64 fp16 = 128 B + 16 pad
#define TILEB (128 * ROWB)          // 18432 per matrix
#define STAGEB (2 * TILEB)          // A + B = 36864
#define GSMEM (2 * STAGEB)          // 73728

__global__ __launch_bounds__(256)
void gemm_hmma(const __half* __restrict__ A, const __half* __restrict__ B,
               float* __restrict__ C, int M, int N, int K, int mode)
{
    extern __shared__ char smraw[];
    const uint32_t sb = smem_u32(smraw);

    const int tid = threadIdx.x, wid = tid >> 5, lane = tid & 31;
    const int bm = blockIdx.y * BM, bn = blockIdx.x * BN;
    const int wm = wid >> 1, wn = wid & 1;

    const __half* A_p = A + (size_t)bm * K;
    const __half* B_p = B + (size_t)bn * K;

    const int nk = K / BK;

    auto load_mat = [&](uint32_t dst, const __half* src, size_t kofs) {
#pragma unroll
        for (int i = 0; i < 4; ++i) {
            const int v = tid + i * 256;       // 128 rows x 8 chunks = 1024
            const int row = v >> 3, c = v & 7;
            cp16(dst + row * ROWB + c * 16, src + (size_t)row * K + kofs + c * 8);
        }
    };
    auto stage_load = [&](int s, int kc) {
        const uint32_t base = sb + s * STAGEB;
        const size_t kofs = (size_t)kc * BK;
        load_mat(base,         A_p, kofs);
        load_mat(base + TILEB, B_p, kofs);
    };

    float acc[16][4];
#pragma unroll
    for (int i = 0; i < 16; ++i)
#pragma unroll
        for (int j = 0; j < 4; ++j) acc[i][j] = 0.f;

    stage_load(0, 0); cp_commit();
    stage_load(1, 1); cp_commit();
    cp_wait<1>();
    __syncthreads();

    for (int c = 0; c < nk; ++c) {
        const int s = c & 1;
        const uint32_t Ah = sb + s * STAGEB;
        const uint32_t Bh = Ah + TILEB;

#pragma unroll
        for (int ks = 0; ks < 4; ++ks) {
            uint32_t ah[2][4];
#pragma unroll
            for (int mt = 0; mt < 2; ++mt) {
                const uint32_t ro = (uint32_t)(wm * 32 + mt * 16 + (lane & 15)) * ROWB
                                  + ks * 32 + (lane >> 4) * 16;
                ldsm4(ah[mt], Ah + ro);
            }
#pragma unroll
            for (int bt = 0; bt < 4; ++bt) {
                const uint32_t ro = (uint32_t)(wn * 64 + bt * 16 + (lane & 15)) * ROWB
                                  + ks * 32 + (lane >> 4) * 16;
                uint32_t bh[4];
                ldsm4(bh, Bh + ro);
                const uint32_t b0h[2] = { bh[0], bh[2] }, b1h[2] = { bh[1], bh[3] };
#pragma unroll
                for (int mt = 0; mt < 2; ++mt) {
                    mma16816(acc[mt * 8 + bt * 2 + 0], ah[mt], b0h);
                    mma16816(acc[mt * 8 + bt * 2 + 1], ah[mt], b1h);
                }
            }
        }

        __syncthreads();
        if (c + 2 < nk) {
            stage_load(s, c + 2);
            cp_commit();
            cp_wait<1>();
        } else {
            cp_wait<0>();
        }
        __syncthreads();
    }

    const int group = bn >> 11;       // 0=q 1=k 2=v 3=g (mode 1 only)

    // ---- fused clamp+RMSNorm for q,k (mode 1) ----
    float* ssm = (float*)smraw;
    if (mode && group < 2) {
        float ssp[2][2] = { {0.f, 0.f}, {0.f, 0.f} };
#pragma unroll
        for (int mt = 0; mt < 2; ++mt)
#pragma unroll
            for (int bt = 0; bt < 4; ++bt)
#pragma unroll
                for (int half = 0; half < 2; ++half) {
                    float* a = acc[mt * 8 + bt * 2 + half];
#pragma unroll
                    for (int q = 0; q < 4; ++q) {
                        float v = fminf(fmaxf(a[q], -FP16MAX), FP16MAX);
                        a[q] = v;
                        ssp[mt][q >> 1] += v * v;
                    }
                }
#pragma unroll
        for (int mt = 0; mt < 2; ++mt)
#pragma unroll
            for (int hh = 0; hh < 2; ++hh) {
                float s0 = ssp[mt][hh];
                s0 += __shfl_xor_sync(0xffffffffu, s0, 1);
                s0 += __shfl_xor_sync(0xffffffffu, s0, 2);
                if ((lane & 3) == 0) {
                    const int row = wm * 32 + mt * 16 + (lane >> 2) + hh * 8;
                    ssm[wn * 128 + row] = s0;
                }
            }
        __syncthreads();
        const float post = (group == 0) ? ATTN_SCALE_L2E : 1.0f;
#pragma unroll
        for (int mt = 0; mt < 2; ++mt)
#pragma unroll
            for (int hh = 0; hh < 2; ++hh) {
                const int row = wm * 32 + mt * 16 + (lane >> 2) + hh * 8;
                const float tot = ssm[row] + ssm[128 + row];
                const float sc = rsqrtf(tot * (1.0f / 128.0f) + RMS_EPS) * post;
#pragma unroll
                for (int bt = 0; bt < 4; ++bt)
#pragma unroll
                    for (int half = 0; half < 2; ++half) {
                        acc[mt * 8 + bt * 2 + half][hh * 2 + 0] *= sc;
                        acc[mt * 8 + bt * 2 + half][hh * 2 + 1] *= sc;
                    }
            }
    }

    if (mode) {
        // q,k,v,gate all fp16. Layout [b][h][s][d].
        const int hh = (bn >> 7) & 15;
        __half* dsth = (group == 0) ? g_qh : (group == 1) ? g_kh
                     : (group == 2) ? g_vh : g_gate;
#pragma unroll
        for (int mt = 0; mt < 2; ++mt)
#pragma unroll
            for (int bt = 0; bt < 4; ++bt)
#pragma unroll
                for (int half = 0; half < 2; ++half) {
                    const int d = wn * 64 + bt * 16 + half * 8 + (lane & 3) * 2;
                    float* a = acc[mt * 8 + bt * 2 + half];
#pragma unroll
                    for (int rr = 0; rr < 2; ++rr) {
                        const int row = bm + wm * 32 + mt * 16 + (lane >> 2) + rr * 8;
                        const int bb = row >> 11, s = row & 2047;
                        const size_t idx = ((size_t)(bb * HEADS + hh) * SEQ + s) * HD + d;
                        *(uint32_t*)(dsth + idx) = roundh2(a[rr * 2 + 0], a[rr * 2 + 1]);
                    }
                }
    } else {
#pragma unroll
        for (int mt = 0; mt < 2; ++mt)
#pragma unroll
            for (int bt = 0; bt < 4; ++bt)
#pragma unroll
                for (int half = 0; half < 2; ++half) {
                    const int col = bn + wn * 64 + bt * 16 + half * 8 + (lane & 3) * 2;
                    const int r0 = bm + wm * 32 + mt * 16 + (lane >> 2);
                    float* a = acc[mt * 8 + bt * 2 + half];
                    *(float2*)(C + (size_t)r0 * N + col)       = make_float2(a[0], a[1]);
                    *(float2*)(C + (size_t)(r0 + 8) * N + col) = make_float2(a[2], a[3]);
                }
    }
}

// ---------------- HMMA fp16 1-term flash attention ----------------
// 512 threads = 16 warps, each warp 16 q rows -> 256 q rows per CTA.
// KV chunks of 64, double buffered. Softmax in exp2 domain (scale folded into q).
#define AROWB 272                        // 128 fp16 = 256 B + 16 pad
#define QROWS 256
#define QT (QROWS * AROWB)               // 69632
#define KVR 64
#define KVB (KVR * AROWB)                // 17408
#define STG (2 * KVB)                    // k + v = 34816
#define ATTN_SMEM (QT + 2 * STG)         // 139264

__global__ __launch_bounds__(512, 1)
void attn_hmma()
{
    extern __shared__ char smraw[];
    const uint32_t sb = smem_u32(smraw);

    const int tid = threadIdx.x, w = tid >> 5, lane = tid & 31;
    const int qt = blockIdx.x, h = blockIdx.y, b = blockIdx.z;
    const size_t hb = ((size_t)b * HEADS + h) * SEQ;

    const __half* Qh_g = g_qh + (hb + qt * QROWS) * HD;
    const __half* Kh_g = g_kh + hb * HD;
    const __half* Vh_g = g_vh + hb * HD;

    auto loadKV = [&](int s, int kt) {
        const uint32_t base = sb + QT + s * STG;
        const size_t kv0 = (size_t)kt * KVR;
#pragma unroll
        for (int i = 0; i < 2; ++i) {
            const int v = tid + i * 512;         // 64 rows x 16 chunks
            const int row = v >> 4, c = v & 15;
            const uint32_t so = base + row * AROWB + c * 16;
            const size_t go = (kv0 + row) * HD + c * 8;
            cp16(so,       Kh_g + go);
            cp16(so + KVB, Vh_g + go);
        }
    };

#pragma unroll
    for (int i = 0; i < 8; ++i) {
        const int v = tid + i * 512;
        const int row = v >> 4, c = v & 15;
        cp16(sb + row * AROWB + c * 16, Qh_g + (size_t)row * HD + c * 8);
    }
    loadKV(0, 0); cp_commit();
    loadKV(1, 1); cp_commit();
    cp_wait<1>();
    __syncthreads();

    float oacc[16][4];
#pragma unroll
    for (int i = 0; i < 16; ++i)
#pragma unroll
        for (int j = 0; j < 4; ++j) oacc[i][j] = 0.f;
    float m0 = -INFINITY, m1 = -INFINITY, l0 = 0.f, l1 = 0.f;

    const int nkt = SEQ / KVR;   // 32
    for (int c = 0; c < nkt; ++c) {
        const int s = c & 1;
        const uint32_t kbase = sb + QT + s * STG;

        // ---- S = q @ K^T (1-term, 16q x 64kv) ----
        float sacc[8][4];
#pragma unroll
        for (int i = 0; i < 8; ++i)
#pragma unroll
            for (int j = 0; j < 4; ++j) sacc[i][j] = 0.f;

#pragma unroll
        for (int kt = 0; kt < 8; ++kt) {
            uint32_t ah[4];
            const uint32_t qo = (uint32_t)(w * 16 + (lane & 15)) * AROWB
                              + kt * 32 + (lane >> 4) * 16;
            ldsm4(ah, sb + qo);
#pragma unroll
            for (int g = 0; g < 4; ++g) {
                const uint32_t ko = kbase + (uint32_t)(g * 16 + (lane & 15)) * AROWB
                                  + kt * 32 + (lane >> 4) * 16;
                uint32_t bh[4];
                ldsm4(bh, ko);
                const uint32_t b0[2] = { bh[0], bh[2] }, b1[2] = { bh[1], bh[3] };
                mma16816(sacc[2 * g + 0], ah, b0);
                mma16816(sacc[2 * g + 1], ah, b1);
            }
        }

        // ---- online softmax (exp2 domain) ----
        float mx0 = -INFINITY, mx1 = -INFINITY;
#pragma unroll
        for (int j = 0; j < 8; ++j) {
            mx0 = fmaxf(mx0, fmaxf(sacc[j][0], sacc[j][1]));
            mx1 = fmaxf(mx1, fmaxf(sacc[j][2], sacc[j][3]));
        }
        mx0 = fmaxf(mx0, __shfl_xor_sync(0xffffffffu, mx0, 1));
        mx0 = fmaxf(mx0, __shfl_xor_sync(0xffffffffu, mx0, 2));
        mx1 = fmaxf(mx1, __shfl_xor_sync(0xffffffffu, mx1, 1));
        mx1 = fmaxf(mx1, __shfl_xor_sync(0xffffffffu, mx1, 2));
        const float mn0 = fmaxf(m0, mx0), mn1 = fmaxf(m1, mx1);
        const float corr0 = exp2fa(m0 - mn0), corr1 = exp2fa(m1 - mn1);
        m0 = mn0; m1 = mn1;
        float rs0 = 0.f, rs1 = 0.f;
#pragma unroll
        for (int j = 0; j < 8; ++j) {
            sacc[j][0] = exp2fa(sacc[j][0] - mn0);
            sacc[j][1] = exp2fa(sacc[j][1] - mn0);
            sacc[j][2] = exp2fa(sacc[j][2] - mn1);
            sacc[j][3] = exp2fa(sacc[j][3] - mn1);
            rs0 += sacc[j][0] + sacc[j][1];
            rs1 += sacc[j][2] + sacc[j][3];
        }
        rs0 += __shfl_xor_sync(0xffffffffu, rs0, 1);
        rs0 += __shfl_xor_sync(0xffffffffu, rs0, 2);
        rs1 += __shfl_xor_sync(0xffffffffu, rs1, 1);
        rs1 += __shfl_xor_sync(0xffffffffu, rs1, 2);
        l0 = l0 * corr0 + rs0;
        l1 = l1 * corr1 + rs1;
#pragma unroll
        for (int n = 0; n < 16; ++n) {
            oacc[n][0] *= corr0; oacc[n][1] *= corr0;
            oacc[n][2] *= corr1; oacc[n][3] *= corr1;
        }

        // ---- O += P @ V (P rounded to fp16 per k16 group) ----
#pragma unroll
        for (int kc = 0; kc < 4; ++kc) {
            uint32_t pa[4];
            pa[0] = roundh2(sacc[2 * kc][0],     sacc[2 * kc][1]);
            pa[1] = roundh2(sacc[2 * kc][2],     sacc[2 * kc][3]);
            pa[2] = roundh2(sacc[2 * kc + 1][0], sacc[2 * kc + 1][1]);
            pa[3] = roundh2(sacc[2 * kc + 1][2], sacc[2 * kc + 1][3]);
#pragma unroll
            for (int g2 = 0; g2 < 8; ++g2) {
                const uint32_t vo = kbase + KVB
                                  + (uint32_t)(kc * 16 + (lane & 15)) * AROWB
                                  + (g2 * 16 + (lane >> 4) * 8) * 2;
                uint32_t vh[4];
                ldsm4t(vh, vo);
                const uint32_t b0[2] = { vh[0], vh[1] }, b1[2] = { vh[2], vh[3] };
                mma16816(oacc[2 * g2 + 0], pa, b0);
                mma16816(oacc[2 * g2 + 1], pa, b1);
            }
        }

        __syncthreads();
        if (c + 2 < nkt) {
            loadKV(s, c + 2);
            cp_commit();
            cp_wait<1>();
        } else {
            cp_wait<0>();
        }
        __syncthreads();
    }

    // ---- epilogue: O/l, sigmoid gate, rounded fp16 for GEMM2 ----
    const float inv0 = 1.0f / l0, inv1 = 1.0f / l1;
    const int r0 = w * 16 + (lane >> 2);
#pragma unroll
    for (int n = 0; n < 16; ++n) {
        const int d = n * 8 + (lane & 3) * 2;
#pragma unroll
        for (int rr = 0; rr < 2; ++rr) {
            const int qrow = qt * QROWS + r0 + rr * 8;
            const float inv = rr ? inv1 : inv0;
            const uint32_t gw = *(const uint32_t*)(g_gate + (hb + qrow) * HD + d);
            const float2 gv = __half22float2(*(const __half2*)&gw);
            const float sg0 = 1.0f / (1.0f + __expf(-gv.x));
            const float sg1 = 1.0f / (1.0f + __expf(-gv.y));
            const float x = sg0 * oacc[n][rr * 2 + 0] * inv;
            const float y = sg1 * oacc[n][rr * 2 + 1] * inv;
            const size_t o = (size_t)(b * SEQ + qrow) * DMODEL + h * HD + d;
            *(uint32_t*)(g_th + o) = roundh2(x, y);
        }
    }
}

// ---------------------------------------------------------------------------
extern "C" void kernel_launch(void* const* d_in, const int* in_sizes, int n_in,
                              void* d_out, int out_size)
{
    const float* hidden = (const float*)d_in[0];
    const float* W_in   = (const float*)d_in[1];
    const float* W_out  = (const float*)d_in[2];
    float* out = (float*)d_out;

    __half *ah, *win, *wo, *th;
    cudaGetSymbolAddress((void**)&ah,  g_ah);
    cudaGetSymbolAddress((void**)&win, g_win);
    cudaGetSymbolAddress((void**)&wo,  g_wo);
    cudaGetSymbolAddress((void**)&th,  g_th);

    cudaFuncSetAttribute(gemm_hmma,
                         cudaFuncAttributeMaxDynamicSharedMemorySize, GSMEM);
    cudaFuncSetAttribute(attn_hmma,
                         cudaFuncAttributeMaxDynamicSharedMemorySize, ATTN_SMEM);

    // prep: hidden -> fp16; W_in -> fp16 T; W_out -> fp16 T
    round_plain<<<1024, 256>>>(hidden, ah, (size_t)ROWS * DMODEL / 4);
    transpose_round<<<dim3(NPROJ / 32, DMODEL / 32), dim3(32, 8)>>>(W_in, win,
                                                                    DMODEL, NPROJ);
    transpose_round<<<dim3(DMODEL / 32, DMODEL / 32), dim3(32, 8)>>>(W_out, wo,
                                                                     DMODEL, DMODEL);

    // 1) proj GEMM (1-term fp16) -> q/k/v/gate fp16 (+rmsnorm, exp2-scale on q)
    gemm_hmma<<<dim3(NPROJ / BN, ROWS / BM), 256, GSMEM>>>(
        ah, win, nullptr, ROWS, NPROJ, DMODEL, 1);

    // 2) fp16 1-term flash attention (exp2 softmax) + sigmoid gate -> g_th
    attn_hmma<<<dim3(SEQ / QROWS, HEADS, NB), 512, ATTN_SMEM>>>();

    // 3) out = att @ W_out (1-term fp16)
    gemm_hmma<<<dim3(DMODEL / BN, ROWS / BM), 256, GSMEM>>>(
        th, wo, out, ROWS, DMODEL, DMODEL, 0);
}